// round 1
// baseline (speedup 1.0000x reference)
#include <cuda_runtime.h>
#include <math.h>

// ---------------- problem constants ----------------
#define Bn   64
#define Qn   64
#define Tn   448
#define Dn   512
#define FDn  1024
#define Hn   8
#define NLn  2
#define FFn  2048
#define Sn   512           // Qn + Tn
#define DHn  64
#define BSr  (Bn*Sn)       // 32768 rows
#define BTr  (Bn*Tn)       // 28672 rows

// ---------------- scratch (device globals: allocation-free) ----------------
__device__ float g_x  [BSr*Dn];
__device__ float g_q  [BSr*Dn];
__device__ float g_k  [BSr*Dn];
__device__ float g_v  [BSr*Dn];
__device__ float g_ctx[BSr*Dn];
__device__ float g_t1 [BSr*Dn];
__device__ float g_h  [BSr*FFn];

// ---------------- fp32 tiled GEMM: C = A[MxK] @ B[KxN] + bias (+epilogue) ----------------
// EPI: 0 = bias only, 1 = bias + exact GELU, 2 = bias + residual
#define BM 128
#define BN 128
#define BKs 8

template<int EPI>
__global__ void __launch_bounds__(256) sgemm_k(
    const float* __restrict__ A, const float* __restrict__ Bm,
    const float* __restrict__ bias, const float* __restrict__ R,
    float* __restrict__ C, int M, int N, int K)
{
    __shared__ float As[BKs][BM];
    __shared__ float Bs[BKs][BN];
    const int tid  = threadIdx.x;
    const int brow = blockIdx.y, bcol = blockIdx.x;
    const float* Ab = A + (size_t)brow * BM * K;
    const float* Bb = Bm + bcol * BN;
    const int aRow = tid >> 1,  aCol = (tid & 1) * 4;   // 128 rows x 2 float4
    const int bRow = tid >> 5,  bCol = (tid & 31) * 4;  // 8 rows x 32 float4
    const int tr = (tid >> 4) * 8, tc = (tid & 15) * 8;

    float acc[8][8];
#pragma unroll
    for (int i = 0; i < 8; i++)
#pragma unroll
        for (int j = 0; j < 8; j++) acc[i][j] = 0.f;

    for (int k0 = 0; k0 < K; k0 += BKs) {
        float4 a4 = *(const float4*)(Ab + (size_t)aRow * K + k0 + aCol);
        As[aCol+0][aRow] = a4.x; As[aCol+1][aRow] = a4.y;
        As[aCol+2][aRow] = a4.z; As[aCol+3][aRow] = a4.w;
        *(float4*)&Bs[bRow][bCol] = *(const float4*)(Bb + (size_t)(k0 + bRow) * N + bCol);
        __syncthreads();
#pragma unroll
        for (int kk = 0; kk < BKs; kk++) {
            float ar[8], br[8];
#pragma unroll
            for (int i = 0; i < 8; i++) ar[i] = As[kk][tr + i];
#pragma unroll
            for (int j = 0; j < 8; j++) br[j] = Bs[kk][tc + j];
#pragma unroll
            for (int i = 0; i < 8; i++)
#pragma unroll
                for (int j = 0; j < 8; j++) acc[i][j] = fmaf(ar[i], br[j], acc[i][j]);
        }
        __syncthreads();
    }

    const int r0 = brow * BM + tr, c0 = bcol * BN + tc;
#pragma unroll
    for (int i = 0; i < 8; i++) {
        size_t roff = (size_t)(r0 + i) * N;
#pragma unroll
        for (int j = 0; j < 8; j += 4) {
            int c = c0 + j;
            float v0 = acc[i][j+0] + bias[c+0];
            float v1 = acc[i][j+1] + bias[c+1];
            float v2 = acc[i][j+2] + bias[c+2];
            float v3 = acc[i][j+3] + bias[c+3];
            if (EPI == 1) {
                v0 = 0.5f * v0 * (1.f + erff(v0 * 0.70710678118654752f));
                v1 = 0.5f * v1 * (1.f + erff(v1 * 0.70710678118654752f));
                v2 = 0.5f * v2 * (1.f + erff(v2 * 0.70710678118654752f));
                v3 = 0.5f * v3 * (1.f + erff(v3 * 0.70710678118654752f));
            } else if (EPI == 2) {
                float4 rr = *(const float4*)(R + roff + c);
                v0 += rr.x; v1 += rr.y; v2 += rr.z; v3 += rr.w;
            }
            float4 o; o.x = v0; o.y = v1; o.z = v2; o.w = v3;
            *(float4*)(C + roff + c) = o;
        }
    }
}

// ---------------- block reduction helper (128 threads = 4 warps) ----------------
__device__ __forceinline__ float blockSum128(float v, float* ws)
{
#pragma unroll
    for (int o = 16; o > 0; o >>= 1) v += __shfl_xor_sync(0xffffffffu, v, o);
    if ((threadIdx.x & 31) == 0) ws[threadIdx.x >> 5] = v;
    __syncthreads();
    v = ws[0] + ws[1] + ws[2] + ws[3];
    __syncthreads();
    return v;
}

// ---------------- LayerNorm over rows of D=512 (128 threads/row) ----------------
// remap=1: input row r in [0, B*T) -> output row (r/T)*S + Q + (r%T)  (video path)
__global__ void ln_kernel(const float* __restrict__ in, const float* __restrict__ gg,
                          const float* __restrict__ bb, float* __restrict__ out, int remap)
{
    __shared__ float ws[4];
    const int r = blockIdx.x;
    const float* row = in + (size_t)r * Dn;
    const int orow = remap ? ((r / Tn) * Sn + Qn + (r % Tn)) : r;
    const int t = threadIdx.x;
    float val[4]; float s = 0.f;
#pragma unroll
    for (int i = 0; i < 4; i++) { val[i] = row[t + i * 128]; s += val[i]; }
    s = blockSum128(s, ws);
    const float mean = s * (1.0f / Dn);
    float vs = 0.f;
#pragma unroll
    for (int i = 0; i < 4; i++) { float d = val[i] - mean; vs += d * d; }
    vs = blockSum128(vs, ws);
    const float rstd = rsqrtf(vs * (1.0f / Dn) + 1e-12f);
    float* op = out + (size_t)orow * Dn;
#pragma unroll
    for (int i = 0; i < 4; i++) {
        int c = t + i * 128;
        op[c] = (val[i] - mean) * rstd * gg[c] + bb[c];
    }
}

// ---------------- embed: concat(question, video) + pos + mod, then LN ----------------
__global__ void embed_ln_kernel(const float* __restrict__ question,
                                const float* __restrict__ pos, const float* __restrict__ mod,
                                const float* __restrict__ gg, const float* __restrict__ bb,
                                float* __restrict__ x)
{
    __shared__ float ws[4];
    const int row = blockIdx.x;              // b*S + s
    const int s = row % Sn, b = row / Sn;
    const int t = threadIdx.x;
    const float* base = (s < Qn) ? (question + (size_t)(b * Qn + s) * Dn)
                                 : (x + (size_t)row * Dn);
    const float* pe = pos + (size_t)s * Dn;
    const float* me = mod + (s >= Qn ? Dn : 0);
    float val[4]; float sum = 0.f;
#pragma unroll
    for (int i = 0; i < 4; i++) {
        int c = t + i * 128;
        val[i] = base[c] + pe[c] + me[c];
        sum += val[i];
    }
    sum = blockSum128(sum, ws);
    const float mean = sum * (1.0f / Dn);
    float vs = 0.f;
#pragma unroll
    for (int i = 0; i < 4; i++) { float d = val[i] - mean; vs += d * d; }
    vs = blockSum128(vs, ws);
    const float rstd = rsqrtf(vs * (1.0f / Dn) + 1e-12f);
    float* op = x + (size_t)row * Dn;
#pragma unroll
    for (int i = 0; i < 4; i++) {
        int c = t + i * 128;
        op[c] = (val[i] - mean) * rstd * gg[c] + bb[c];
    }
}

// ---------------- flash-style attention: 64-query tile per block ----------------
// grid = (S/64, B*H), block = 256 (16x16 threads, each owns 4x4 of the 64x64 tile)
#define ATTN_SMEM_FLOATS (4 * 64 * 65 + 4 * 64)
#define ATTN_SMEM_BYTES  (ATTN_SMEM_FLOATS * 4)

__global__ void __launch_bounds__(256) attn_kernel(
    const float* __restrict__ q, const float* __restrict__ k, const float* __restrict__ v,
    const int* __restrict__ mask, float* __restrict__ ctx)
{
    extern __shared__ float sm[];
    float* Qs    = sm;                 // [64][65]
    float* Ks    = Qs + 64 * 65;
    float* Vs    = Ks + 64 * 65;
    float* Ps    = Vs + 64 * 65;
    float* mrow  = Ps + 64 * 65;       // [64]
    float* lrow  = mrow + 64;
    float* scl   = lrow + 64;
    float* maskb = scl + 64;

    const int tid = threadIdx.x;
    const int qt = blockIdx.x;
    const int bh = blockIdx.y;
    const int b = bh >> 3, h = bh & 7;
    const int ty = tid >> 4, tx = tid & 15;

    // load Q tile (scaled by 1/sqrt(DH) = 0.125)
    {
        const int c = (tid & 15) * 4;
        for (int r = tid >> 4; r < 64; r += 16) {
            const float* src = q + (size_t)(b * Sn + qt * 64 + r) * Dn + h * DHn + c;
            float4 a = *(const float4*)src;
            Qs[r * 65 + c + 0] = a.x * 0.125f;
            Qs[r * 65 + c + 1] = a.y * 0.125f;
            Qs[r * 65 + c + 2] = a.z * 0.125f;
            Qs[r * 65 + c + 3] = a.w * 0.125f;
        }
    }
    if (tid < 64) { mrow[tid] = -1e30f; lrow[tid] = 0.f; }

    float o[4][4];
#pragma unroll
    for (int i = 0; i < 4; i++)
#pragma unroll
        for (int j = 0; j < 4; j++) o[i][j] = 0.f;

    for (int kt = 0; kt < Sn / 64; kt++) {
        // load K/V tiles + mask bias for this tile
        {
            const int c = (tid & 15) * 4;
            for (int r = tid >> 4; r < 64; r += 16) {
                const size_t goff = (size_t)(b * Sn + kt * 64 + r) * Dn + h * DHn + c;
                float4 a = *(const float4*)(k + goff);
                Ks[r * 65 + c + 0] = a.x; Ks[r * 65 + c + 1] = a.y;
                Ks[r * 65 + c + 2] = a.z; Ks[r * 65 + c + 3] = a.w;
                float4 vv = *(const float4*)(v + goff);
                Vs[r * 65 + c + 0] = vv.x; Vs[r * 65 + c + 1] = vv.y;
                Vs[r * 65 + c + 2] = vv.z; Vs[r * 65 + c + 3] = vv.w;
            }
            if (tid < 64)
                maskb[tid] = (mask[b * Sn + kt * 64 + tid] == 0) ? -1e30f : 0.f;
        }
        __syncthreads();

        // S tile = Qs @ Ks^T (+ mask bias)
        {
            float sreg[4][4];
#pragma unroll
            for (int i = 0; i < 4; i++)
#pragma unroll
                for (int j = 0; j < 4; j++) sreg[i][j] = 0.f;
#pragma unroll 8
            for (int d = 0; d < 64; d++) {
                float ar[4], br[4];
#pragma unroll
                for (int i = 0; i < 4; i++) ar[i] = Qs[(ty * 4 + i) * 65 + d];
#pragma unroll
                for (int j = 0; j < 4; j++) br[j] = Ks[(tx * 4 + j) * 65 + d];
#pragma unroll
                for (int i = 0; i < 4; i++)
#pragma unroll
                    for (int j = 0; j < 4; j++) sreg[i][j] = fmaf(ar[i], br[j], sreg[i][j]);
            }
#pragma unroll
            for (int i = 0; i < 4; i++)
#pragma unroll
                for (int j = 0; j < 4; j++)
                    Ps[(ty * 4 + i) * 65 + tx * 4 + j] = sreg[i][j] + maskb[tx * 4 + j];
        }
        __syncthreads();

        // online softmax row pass (one thread per query row)
        if (tid < 64) {
            const int qr = tid;
            float mold = mrow[qr];
            float tmax = -1e30f;
#pragma unroll 8
            for (int j = 0; j < 64; j++) tmax = fmaxf(tmax, Ps[qr * 65 + j]);
            float mnew = fmaxf(mold, tmax);
            float f = __expf(mold - mnew);
            float ls = 0.f;
#pragma unroll 8
            for (int j = 0; j < 64; j++) {
                float p = __expf(Ps[qr * 65 + j] - mnew);
                Ps[qr * 65 + j] = p;
                ls += p;
            }
            lrow[qr] = lrow[qr] * f + ls;
            mrow[qr] = mnew;
            scl[qr] = f;
        }
        __syncthreads();

        // O = O*f + P @ V
        {
#pragma unroll
            for (int i = 0; i < 4; i++) {
                float f = scl[ty * 4 + i];
#pragma unroll
                for (int j = 0; j < 4; j++) o[i][j] *= f;
            }
#pragma unroll 8
            for (int kc = 0; kc < 64; kc++) {
                float pr[4], vr[4];
#pragma unroll
                for (int i = 0; i < 4; i++) pr[i] = Ps[(ty * 4 + i) * 65 + kc];
#pragma unroll
                for (int j = 0; j < 4; j++) vr[j] = Vs[kc * 65 + tx * 4 + j];
#pragma unroll
                for (int i = 0; i < 4; i++)
#pragma unroll
                    for (int j = 0; j < 4; j++) o[i][j] = fmaf(pr[i], vr[j], o[i][j]);
            }
        }
        __syncthreads();
    }

    // write ctx in [B,S,D] layout (d = h*64 + col)
#pragma unroll
    for (int i = 0; i < 4; i++) {
        const int qr = ty * 4 + i;
        const float inv = 1.0f / lrow[qr];
        float4 ov;
        ov.x = o[i][0] * inv; ov.y = o[i][1] * inv;
        ov.z = o[i][2] * inv; ov.w = o[i][3] * inv;
        *(float4*)(ctx + (size_t)(b * Sn + qt * 64 + qr) * Dn + h * DHn + tx * 4) = ov;
    }
}

// ---------------- host orchestration ----------------
extern "C" void kernel_launch(void* const* d_in, const int* in_sizes, int n_in,
                              void* d_out, int out_size)
{
    const float* video    = (const float*)d_in[0];
    const float* question = (const float*)d_in[1];
    const int*   mask     = (const int*)  d_in[2];
    const float* pos_emb  = (const float*)d_in[3];
    const float* mod_emb  = (const float*)d_in[4];
    const float* Wv       = (const float*)d_in[5];
    const float* bv       = (const float*)d_in[6];
    const float* nv_g     = (const float*)d_in[7];
    const float* nv_b     = (const float*)d_in[8];
    const float* emb_g    = (const float*)d_in[9];
    const float* emb_b    = (const float*)d_in[10];
    const float* Wq       = (const float*)d_in[11];
    const float* bq       = (const float*)d_in[12];
    const float* Wk       = (const float*)d_in[13];
    const float* bk       = (const float*)d_in[14];
    const float* Wva      = (const float*)d_in[15];
    const float* bva      = (const float*)d_in[16];
    const float* Wo       = (const float*)d_in[17];
    const float* bo       = (const float*)d_in[18];
    const float* ln1_g    = (const float*)d_in[19];
    const float* ln1_b    = (const float*)d_in[20];
    const float* W1       = (const float*)d_in[21];
    const float* b1       = (const float*)d_in[22];
    const float* W2       = (const float*)d_in[23];
    const float* b2       = (const float*)d_in[24];
    const float* ln2_g    = (const float*)d_in[25];
    const float* ln2_b    = (const float*)d_in[26];

    float *x, *q, *k, *v, *ctx, *t1, *hbuf;
    cudaGetSymbolAddress((void**)&x,    g_x);
    cudaGetSymbolAddress((void**)&q,    g_q);
    cudaGetSymbolAddress((void**)&k,    g_k);
    cudaGetSymbolAddress((void**)&v,    g_v);
    cudaGetSymbolAddress((void**)&ctx,  g_ctx);
    cudaGetSymbolAddress((void**)&t1,   g_t1);
    cudaGetSymbolAddress((void**)&hbuf, g_h);

    static bool attr_set = false;
    if (!attr_set) {
        cudaFuncSetAttribute(attn_kernel, cudaFuncAttributeMaxDynamicSharedMemorySize,
                             ATTN_SMEM_BYTES);
        attr_set = true;
    }

    // 1) video projection: [B*T, FD] @ [FD, D] + bv  -> t1
    sgemm_k<0><<<dim3(Dn / BN, BTr / BM), 256>>>(video, Wv, bv, nullptr, t1, BTr, Dn, FDn);
    // 2) LN(video) into x rows [b*S + Q + t]
    ln_kernel<<<BTr, 128>>>(t1, nv_g, nv_b, x, 1);
    // 3) concat + pos/mod emb + LN -> x
    embed_ln_kernel<<<BSr, 128>>>(question, pos_emb, mod_emb, emb_g, emb_b, x);

    for (int i = 0; i < NLn; i++) {
        const size_t wD = (size_t)i * Dn * Dn;
        // QKV projections
        sgemm_k<0><<<dim3(Dn / BN, BSr / BM), 256>>>(x, Wq  + wD, bq  + i * Dn, nullptr, q, BSr, Dn, Dn);
        sgemm_k<0><<<dim3(Dn / BN, BSr / BM), 256>>>(x, Wk  + wD, bk  + i * Dn, nullptr, k, BSr, Dn, Dn);
        sgemm_k<0><<<dim3(Dn / BN, BSr / BM), 256>>>(x, Wva + wD, bva + i * Dn, nullptr, v, BSr, Dn, Dn);
        // attention
        attn_kernel<<<dim3(Sn / 64, Bn * Hn), 256, ATTN_SMEM_BYTES>>>(q, k, v, mask, ctx);
        // output projection + residual, then LN -> x
        sgemm_k<2><<<dim3(Dn / BN, BSr / BM), 256>>>(ctx, Wo + wD, bo + i * Dn, x, t1, BSr, Dn, Dn);
        ln_kernel<<<BSr, 128>>>(t1, ln1_g + i * Dn, ln1_b + i * Dn, x, 0);
        // FFN
        sgemm_k<1><<<dim3(FFn / BN, BSr / BM), 256>>>(x, W1 + (size_t)i * Dn * FFn, b1 + i * FFn,
                                                      nullptr, hbuf, BSr, FFn, Dn);
        sgemm_k<2><<<dim3(Dn / BN, BSr / BM), 256>>>(hbuf, W2 + (size_t)i * FFn * Dn, b2 + i * Dn,
                                                     x, t1, BSr, Dn, FFn);
        ln_kernel<<<BSr, 128>>>(t1, ln2_g + i * Dn, ln2_b + i * Dn, x, 0);
    }

    cudaMemcpyAsync(d_out, x, (size_t)BSr * Dn * sizeof(float),
                    cudaMemcpyDeviceToDevice, 0);
}

// round 3
// speedup vs baseline: 1.8286x; 1.8286x over previous
#include <cuda_runtime.h>
#include <cuda_bf16.h>
#include <math.h>
#include <stdint.h>

// ---------------- problem constants ----------------
#define Bn   64
#define Qn   64
#define Tn   448
#define Dn   512
#define FDn  1024
#define Hn   8
#define NLn  2
#define FFn  2048
#define Sn   512           // Qn + Tn
#define DHn  64
#define BSr  (Bn*Sn)       // 32768 rows
#define BTr  (Bn*Tn)       // 28672 rows

// ---------------- scratch (device globals: allocation-free) ----------------
__device__ float g_x  [BSr*Dn];
__device__ float g_q  [BSr*Dn];
__device__ float g_k  [BSr*Dn];
__device__ float g_v  [BSr*Dn];
__device__ float g_ctx[BSr*Dn];
__device__ float g_t1 [BSr*Dn];
__device__ float g_h  [BSr*FFn];

// ---------------- helpers ----------------
__device__ __forceinline__ uint32_t smem_u32(const void* p) {
    uint32_t a;
    asm("{ .reg .u64 t; cvta.to.shared.u64 t, %1; cvt.u32.u64 %0, t; }" : "=r"(a) : "l"(p));
    return a;
}
__device__ __forceinline__ void split_bf16(float x, __nv_bfloat16& h, __nv_bfloat16& l) {
    h = __float2bfloat16_rn(x);
    l = __float2bfloat16_rn(x - __bfloat162float(h));
}
__device__ __forceinline__ uint32_t pack2(__nv_bfloat16 a, __nv_bfloat16 b) {
    __nv_bfloat162 v(a, b);
    return *reinterpret_cast<uint32_t*>(&v);
}
__device__ __forceinline__ void ldsm_x4(uint32_t& r0, uint32_t& r1, uint32_t& r2, uint32_t& r3,
                                        uint32_t addr) {
    asm volatile("ldmatrix.sync.aligned.m8n8.x4.shared.b16 {%0,%1,%2,%3}, [%4];"
                 : "=r"(r0), "=r"(r1), "=r"(r2), "=r"(r3) : "r"(addr));
}
__device__ __forceinline__ void ldsm_x2t(uint32_t& r0, uint32_t& r1, uint32_t addr) {
    asm volatile("ldmatrix.sync.aligned.m8n8.x2.trans.shared.b16 {%0,%1}, [%2];"
                 : "=r"(r0), "=r"(r1) : "r"(addr));
}
__device__ __forceinline__ void mma16816(float* d, const uint32_t* a, const uint32_t* b) {
    asm volatile(
        "mma.sync.aligned.m16n8k16.row.col.f32.bf16.bf16.f32 "
        "{%0,%1,%2,%3}, {%4,%5,%6,%7}, {%8,%9}, {%0,%1,%2,%3};"
        : "+f"(d[0]), "+f"(d[1]), "+f"(d[2]), "+f"(d[3])
        : "r"(a[0]), "r"(a[1]), "r"(a[2]), "r"(a[3]), "r"(b[0]), "r"(b[1]));
}

// ---------------- smem layout for the HMMA GEMM ----------------
#define ASTRIDE 72            // A row stride (bf16 elements): 144B, banks 4r%32 conflict-free
#define BSTRIDE 136           // B row stride (bf16 elements): 272B, 16B-aligned rows
#define SM_AH   0
#define SM_AL   (SM_AH + 128 * ASTRIDE * 2)    // 18432
#define SM_BH   (SM_AL + 128 * ASTRIDE * 2)    // 36864
#define SM_BL   (SM_BH + 64 * BSTRIDE * 2)     // 54272
#define SM_TOTAL (SM_BL + 64 * BSTRIDE * 2)    // 71680 bytes

// ============ HMMA GEMM: C = A[MxK] @ B[KxN] + bias (+epilogue) ============
// 3-pass bf16 split (AhBh + AhBl + AlBh) for ~fp32 accuracy.
// EPI: 0 = bias, 1 = bias + exact GELU, 2 = bias + residual.
// Block tile 128x128, 8 warps (4M x 2N), warp tile 32x64, K-chunk 64.
template<int EPI>
__global__ void __launch_bounds__(256) gemm_tc(
    const float* __restrict__ A, const float* __restrict__ Bm,
    const float* __restrict__ bias, const float* __restrict__ R,
    float* __restrict__ C, int M, int N, int K)
{
    extern __shared__ char smem[];
    const uint32_t sb = smem_u32(smem);
    const int tid = threadIdx.x, wid = tid >> 5, lane = tid & 31;
    const int bx = blockIdx.x, by = blockIdx.y;
    const int warp_m = wid & 3, warp_n = wid >> 2;
    const int gid = lane >> 2, tig = lane & 3;

    const float* Arow = A + (size_t)(by * 128) * K;
    const float* Bblk = Bm + bx * 128;

    float acc[2][8][4];
#pragma unroll
    for (int mt = 0; mt < 2; mt++)
#pragma unroll
        for (int nt = 0; nt < 8; nt++)
#pragma unroll
            for (int e = 0; e < 4; e++) acc[mt][nt][e] = 0.f;

    // precomputed fragment base addresses (byte offsets into smem)
    const uint32_t a_off = (uint32_t)((warp_m * 32 + (lane & 15)) * ASTRIDE + (lane >> 4) * 8) * 2;
    const uint32_t b_off = (uint32_t)((lane & 15) * BSTRIDE + warp_n * 64) * 2;

    const int nchunks = K >> 6;
    for (int kc = 0; kc < nchunks; kc++) {
        // ---- convert A chunk: 128 rows x 64 cols f32 -> bf16 hi/lo, row-major ----
#pragma unroll
        for (int it = 0; it < 8; it++) {
            int idx = tid + it * 256;
            int row = idx >> 4, c4 = (idx & 15) * 4;
            float4 a = *(const float4*)(Arow + (size_t)row * K + kc * 64 + c4);
            __nv_bfloat16 hx, lx, hy, ly, hz, lz, hw, lw;
            split_bf16(a.x, hx, lx); split_bf16(a.y, hy, ly);
            split_bf16(a.z, hz, lz); split_bf16(a.w, hw, lw);
            uint32_t off = (uint32_t)(row * ASTRIDE + c4) * 2;
            *(uint2*)(smem + SM_AH + off) = make_uint2(pack2(hx, hy), pack2(hz, hw));
            *(uint2*)(smem + SM_AL + off) = make_uint2(pack2(lx, ly), pack2(lz, lw));
        }
        // ---- convert B chunk: 64 k-rows x 128 n-cols, KEEP [k][n] order (coalesced) ----
#pragma unroll
        for (int it = 0; it < 8; it++) {
            int idx = tid + it * 256;
            int kk = idx >> 5, n4 = (idx & 31) * 4;
            float4 b = *(const float4*)(Bblk + (size_t)(kc * 64 + kk) * N + n4);
            __nv_bfloat16 hx, lx, hy, ly, hz, lz, hw, lw;
            split_bf16(b.x, hx, lx); split_bf16(b.y, hy, ly);
            split_bf16(b.z, hz, lz); split_bf16(b.w, hw, lw);
            uint32_t off = (uint32_t)(kk * BSTRIDE + n4) * 2;
            *(uint2*)(smem + SM_BH + off) = make_uint2(pack2(hx, hy), pack2(hz, hw));
            *(uint2*)(smem + SM_BL + off) = make_uint2(pack2(lx, ly), pack2(lz, lw));
        }
        __syncthreads();

        // ---- MMA over 4 k16 steps x 3 split passes ----
#pragma unroll
        for (int ks = 0; ks < 4; ks++) {
            const uint32_t kb = (uint32_t)(ks * 16) * 2;
            uint32_t ah[2][4], al[2][4];
#pragma unroll
            for (int mt = 0; mt < 2; mt++) {
                uint32_t aa = sb + a_off + (uint32_t)(mt * 16 * ASTRIDE) * 2 + kb;
                ldsm_x4(ah[mt][0], ah[mt][1], ah[mt][2], ah[mt][3], aa + SM_AH);
                ldsm_x4(al[mt][0], al[mt][1], al[mt][2], al[mt][3], aa + SM_AL);
            }
#pragma unroll
            for (int nt = 0; nt < 8; nt++) {
                uint32_t bb = sb + b_off + (uint32_t)(ks * 16 * BSTRIDE + nt * 8) * 2;
                uint32_t bh[2], bl[2];
                ldsm_x2t(bh[0], bh[1], bb + SM_BH);
                ldsm_x2t(bl[0], bl[1], bb + SM_BL);
#pragma unroll
                for (int mt = 0; mt < 2; mt++) {
                    mma16816(acc[mt][nt], ah[mt], bh);
                    mma16816(acc[mt][nt], ah[mt], bl);
                    mma16816(acc[mt][nt], al[mt], bh);
                }
            }
        }
        __syncthreads();
    }

    // ---- epilogue ----
#pragma unroll
    for (int mt = 0; mt < 2; mt++) {
        const int row0 = by * 128 + warp_m * 32 + mt * 16 + gid;
#pragma unroll
        for (int nt = 0; nt < 8; nt++) {
            const int col = bx * 128 + warp_n * 64 + nt * 8 + 2 * tig;
            float2 bs = *(const float2*)(bias + col);
#pragma unroll
            for (int half = 0; half < 2; half++) {
                const int row = row0 + half * 8;
                float v0 = acc[mt][nt][half * 2 + 0] + bs.x;
                float v1 = acc[mt][nt][half * 2 + 1] + bs.y;
                if (EPI == 1) {
                    v0 = 0.5f * v0 * (1.f + erff(v0 * 0.70710678118654752f));
                    v1 = 0.5f * v1 * (1.f + erff(v1 * 0.70710678118654752f));
                } else if (EPI == 2) {
                    float2 rr = *(const float2*)(R + (size_t)row * N + col);
                    v0 += rr.x; v1 += rr.y;
                }
                float2 o; o.x = v0; o.y = v1;
                *(float2*)(C + (size_t)row * N + col) = o;
            }
        }
    }
}

// ---------------- block reduction helper (128 threads = 4 warps) ----------------
__device__ __forceinline__ float blockSum128(float v, float* ws)
{
#pragma unroll
    for (int o = 16; o > 0; o >>= 1) v += __shfl_xor_sync(0xffffffffu, v, o);
    if ((threadIdx.x & 31) == 0) ws[threadIdx.x >> 5] = v;
    __syncthreads();
    v = ws[0] + ws[1] + ws[2] + ws[3];
    __syncthreads();
    return v;
}

// ---------------- LayerNorm over rows of D=512 (128 threads/row) ----------------
__global__ void ln_kernel(const float* __restrict__ in, const float* __restrict__ gg,
                          const float* __restrict__ bb, float* __restrict__ out, int remap)
{
    __shared__ float ws[4];
    const int r = blockIdx.x;
    const float* row = in + (size_t)r * Dn;
    const int orow = remap ? ((r / Tn) * Sn + Qn + (r % Tn)) : r;
    const int t = threadIdx.x;
    float val[4]; float s = 0.f;
#pragma unroll
    for (int i = 0; i < 4; i++) { val[i] = row[t + i * 128]; s += val[i]; }
    s = blockSum128(s, ws);
    const float mean = s * (1.0f / Dn);
    float vs = 0.f;
#pragma unroll
    for (int i = 0; i < 4; i++) { float d = val[i] - mean; vs += d * d; }
    vs = blockSum128(vs, ws);
    const float rstd = rsqrtf(vs * (1.0f / Dn) + 1e-12f);
    float* op = out + (size_t)orow * Dn;
#pragma unroll
    for (int i = 0; i < 4; i++) {
        int c = t + i * 128;
        op[c] = (val[i] - mean) * rstd * gg[c] + bb[c];
    }
}

// ---------------- embed: concat(question, video) + pos + mod, then LN ----------------
__global__ void embed_ln_kernel(const float* __restrict__ question,
                                const float* __restrict__ pos, const float* __restrict__ mod,
                                const float* __restrict__ gg, const float* __restrict__ bb,
                                float* __restrict__ x)
{
    __shared__ float ws[4];
    const int row = blockIdx.x;
    const int s = row % Sn, b = row / Sn;
    const int t = threadIdx.x;
    const float* base = (s < Qn) ? (question + (size_t)(b * Qn + s) * Dn)
                                 : (x + (size_t)row * Dn);
    const float* pe = pos + (size_t)s * Dn;
    const float* me = mod + (s >= Qn ? Dn : 0);
    float val[4]; float sum = 0.f;
#pragma unroll
    for (int i = 0; i < 4; i++) {
        int c = t + i * 128;
        val[i] = base[c] + pe[c] + me[c];
        sum += val[i];
    }
    sum = blockSum128(sum, ws);
    const float mean = sum * (1.0f / Dn);
    float vs = 0.f;
#pragma unroll
    for (int i = 0; i < 4; i++) { float d = val[i] - mean; vs += d * d; }
    vs = blockSum128(vs, ws);
    const float rstd = rsqrtf(vs * (1.0f / Dn) + 1e-12f);
    float* op = x + (size_t)row * Dn;
#pragma unroll
    for (int i = 0; i < 4; i++) {
        int c = t + i * 128;
        op[c] = (val[i] - mean) * rstd * gg[c] + bb[c];
    }
}

// ---------------- flash-style attention: 64-query tile per block ----------------
#define ATTN_SMEM_FLOATS (4 * 64 * 65 + 4 * 64)
#define ATTN_SMEM_BYTES  (ATTN_SMEM_FLOATS * 4)

__global__ void __launch_bounds__(256) attn_kernel(
    const float* __restrict__ q, const float* __restrict__ k, const float* __restrict__ v,
    const int* __restrict__ mask, float* __restrict__ ctx)
{
    extern __shared__ float sm[];
    float* Qs    = sm;
    float* Ks    = Qs + 64 * 65;
    float* Vs    = Ks + 64 * 65;
    float* Ps    = Vs + 64 * 65;
    float* mrow  = Ps + 64 * 65;
    float* lrow  = mrow + 64;
    float* scl   = lrow + 64;
    float* maskb = scl + 64;

    const int tid = threadIdx.x;
    const int qt = blockIdx.x;
    const int bh = blockIdx.y;
    const int b = bh >> 3, h = bh & 7;
    const int ty = tid >> 4, tx = tid & 15;

    {
        const int c = (tid & 15) * 4;
        for (int r = tid >> 4; r < 64; r += 16) {
            const float* src = q + (size_t)(b * Sn + qt * 64 + r) * Dn + h * DHn + c;
            float4 a = *(const float4*)src;
            Qs[r * 65 + c + 0] = a.x * 0.125f;
            Qs[r * 65 + c + 1] = a.y * 0.125f;
            Qs[r * 65 + c + 2] = a.z * 0.125f;
            Qs[r * 65 + c + 3] = a.w * 0.125f;
        }
    }
    if (tid < 64) { mrow[tid] = -1e30f; lrow[tid] = 0.f; }

    float o[4][4];
#pragma unroll
    for (int i = 0; i < 4; i++)
#pragma unroll
        for (int j = 0; j < 4; j++) o[i][j] = 0.f;

    for (int kt = 0; kt < Sn / 64; kt++) {
        {
            const int c = (tid & 15) * 4;
            for (int r = tid >> 4; r < 64; r += 16) {
                const size_t goff = (size_t)(b * Sn + kt * 64 + r) * Dn + h * DHn + c;
                float4 a = *(const float4*)(k + goff);
                Ks[r * 65 + c + 0] = a.x; Ks[r * 65 + c + 1] = a.y;
                Ks[r * 65 + c + 2] = a.z; Ks[r * 65 + c + 3] = a.w;
                float4 vv = *(const float4*)(v + goff);
                Vs[r * 65 + c + 0] = vv.x; Vs[r * 65 + c + 1] = vv.y;
                Vs[r * 65 + c + 2] = vv.z; Vs[r * 65 + c + 3] = vv.w;
            }
            if (tid < 64)
                maskb[tid] = (mask[b * Sn + kt * 64 + tid] == 0) ? -1e30f : 0.f;
        }
        __syncthreads();

        {
            float sreg[4][4];
#pragma unroll
            for (int i = 0; i < 4; i++)
#pragma unroll
                for (int j = 0; j < 4; j++) sreg[i][j] = 0.f;
#pragma unroll 8
            for (int d = 0; d < 64; d++) {
                float ar[4], br[4];
#pragma unroll
                for (int i = 0; i < 4; i++) ar[i] = Qs[(ty * 4 + i) * 65 + d];
#pragma unroll
                for (int j = 0; j < 4; j++) br[j] = Ks[(tx * 4 + j) * 65 + d];
#pragma unroll
                for (int i = 0; i < 4; i++)
#pragma unroll
                    for (int j = 0; j < 4; j++) sreg[i][j] = fmaf(ar[i], br[j], sreg[i][j]);
            }
#pragma unroll
            for (int i = 0; i < 4; i++)
#pragma unroll
                for (int j = 0; j < 4; j++)
                    Ps[(ty * 4 + i) * 65 + tx * 4 + j] = sreg[i][j] + maskb[tx * 4 + j];
        }
        __syncthreads();

        if (tid < 64) {
            const int qr = tid;
            float mold = mrow[qr];
            float tmax = -1e30f;
#pragma unroll 8
            for (int j = 0; j < 64; j++) tmax = fmaxf(tmax, Ps[qr * 65 + j]);
            float mnew = fmaxf(mold, tmax);
            float f = __expf(mold - mnew);
            float ls = 0.f;
#pragma unroll 8
            for (int j = 0; j < 64; j++) {
                float p = __expf(Ps[qr * 65 + j] - mnew);
                Ps[qr * 65 + j] = p;
                ls += p;
            }
            lrow[qr] = lrow[qr] * f + ls;
            mrow[qr] = mnew;
            scl[qr] = f;
        }
        __syncthreads();

        {
#pragma unroll
            for (int i = 0; i < 4; i++) {
                float f = scl[ty * 4 + i];
#pragma unroll
                for (int j = 0; j < 4; j++) o[i][j] *= f;
            }
#pragma unroll 8
            for (int kc = 0; kc < 64; kc++) {
                float pr[4], vr[4];
#pragma unroll
                for (int i = 0; i < 4; i++) pr[i] = Ps[(ty * 4 + i) * 65 + kc];
#pragma unroll
                for (int j = 0; j < 4; j++) vr[j] = Vs[kc * 65 + tx * 4 + j];
#pragma unroll
                for (int i = 0; i < 4; i++)
#pragma unroll
                    for (int j = 0; j < 4; j++) o[i][j] = fmaf(pr[i], vr[j], o[i][j]);
            }
        }
        __syncthreads();
    }

#pragma unroll
    for (int i = 0; i < 4; i++) {
        const int qr = ty * 4 + i;
        const float inv = 1.0f / lrow[qr];
        float4 ov;
        ov.x = o[i][0] * inv; ov.y = o[i][1] * inv;
        ov.z = o[i][2] * inv; ov.w = o[i][3] * inv;
        *(float4*)(ctx + (size_t)(b * Sn + qt * 64 + qr) * Dn + h * DHn + tx * 4) = ov;
    }
}

// ---------------- host orchestration ----------------
extern "C" void kernel_launch(void* const* d_in, const int* in_sizes, int n_in,
                              void* d_out, int out_size)
{
    const float* video    = (const float*)d_in[0];
    const float* question = (const float*)d_in[1];
    const int*   mask     = (const int*)  d_in[2];
    const float* pos_emb  = (const float*)d_in[3];
    const float* mod_emb  = (const float*)d_in[4];
    const float* Wv       = (const float*)d_in[5];
    const float* bv       = (const float*)d_in[6];
    const float* nv_g     = (const float*)d_in[7];
    const float* nv_b     = (const float*)d_in[8];
    const float* emb_g    = (const float*)d_in[9];
    const float* emb_b    = (const float*)d_in[10];
    const float* Wq       = (const float*)d_in[11];
    const float* bq       = (const float*)d_in[12];
    const float* Wk       = (const float*)d_in[13];
    const float* bk       = (const float*)d_in[14];
    const float* Wva      = (const float*)d_in[15];
    const float* bva      = (const float*)d_in[16];
    const float* Wo       = (const float*)d_in[17];
    const float* bo       = (const float*)d_in[18];
    const float* ln1_g    = (const float*)d_in[19];
    const float* ln1_b    = (const float*)d_in[20];
    const float* W1       = (const float*)d_in[21];
    const float* b1       = (const float*)d_in[22];
    const float* W2       = (const float*)d_in[23];
    const float* b2       = (const float*)d_in[24];
    const float* ln2_g    = (const float*)d_in[25];
    const float* ln2_b    = (const float*)d_in[26];

    float *x, *q, *k, *v, *ctx, *t1, *hbuf;
    cudaGetSymbolAddress((void**)&x,    g_x);
    cudaGetSymbolAddress((void**)&q,    g_q);
    cudaGetSymbolAddress((void**)&k,    g_k);
    cudaGetSymbolAddress((void**)&v,    g_v);
    cudaGetSymbolAddress((void**)&ctx,  g_ctx);
    cudaGetSymbolAddress((void**)&t1,   g_t1);
    cudaGetSymbolAddress((void**)&hbuf, g_h);

    static bool attr_set = false;
    if (!attr_set) {
        cudaFuncSetAttribute(attn_kernel, cudaFuncAttributeMaxDynamicSharedMemorySize,
                             ATTN_SMEM_BYTES);
        cudaFuncSetAttribute(gemm_tc<0>, cudaFuncAttributeMaxDynamicSharedMemorySize, SM_TOTAL);
        cudaFuncSetAttribute(gemm_tc<1>, cudaFuncAttributeMaxDynamicSharedMemorySize, SM_TOTAL);
        cudaFuncSetAttribute(gemm_tc<2>, cudaFuncAttributeMaxDynamicSharedMemorySize, SM_TOTAL);
        attr_set = true;
    }

    // 1) video projection: [B*T, FD] @ [FD, D] + bv -> t1
    gemm_tc<0><<<dim3(Dn / 128, BTr / 128), 256, SM_TOTAL>>>(video, Wv, bv, nullptr, t1, BTr, Dn, FDn);
    // 2) LN(video) into x rows [b*S + Q + t]
    ln_kernel<<<BTr, 128>>>(t1, nv_g, nv_b, x, 1);
    // 3) concat + pos/mod emb + LN -> x
    embed_ln_kernel<<<BSr, 128>>>(question, pos_emb, mod_emb, emb_g, emb_b, x);

    for (int i = 0; i < NLn; i++) {
        const size_t wD = (size_t)i * Dn * Dn;
        gemm_tc<0><<<dim3(Dn / 128, BSr / 128), 256, SM_TOTAL>>>(x, Wq  + wD, bq  + i * Dn, nullptr, q, BSr, Dn, Dn);
        gemm_tc<0><<<dim3(Dn / 128, BSr / 128), 256, SM_TOTAL>>>(x, Wk  + wD, bk  + i * Dn, nullptr, k, BSr, Dn, Dn);
        gemm_tc<0><<<dim3(Dn / 128, BSr / 128), 256, SM_TOTAL>>>(x, Wva + wD, bva + i * Dn, nullptr, v, BSr, Dn, Dn);
        attn_kernel<<<dim3(Sn / 64, Bn * Hn), 256, ATTN_SMEM_BYTES>>>(q, k, v, mask, ctx);
        gemm_tc<2><<<dim3(Dn / 128, BSr / 128), 256, SM_TOTAL>>>(ctx, Wo + wD, bo + i * Dn, x, t1, BSr, Dn, Dn);
        ln_kernel<<<BSr, 128>>>(t1, ln1_g + i * Dn, ln1_b + i * Dn, x, 0);
        gemm_tc<1><<<dim3(FFn / 128, BSr / 128), 256, SM_TOTAL>>>(x, W1 + (size_t)i * Dn * FFn, b1 + i * FFn,
                                                                  nullptr, hbuf, BSr, FFn, Dn);
        gemm_tc<2><<<dim3(Dn / 128, BSr / 128), 256, SM_TOTAL>>>(hbuf, W2 + (size_t)i * FFn * Dn, b2 + i * Dn,
                                                                 x, t1, BSr, Dn, FFn);
        ln_kernel<<<BSr, 128>>>(t1, ln2_g + i * Dn, ln2_b + i * Dn, x, 0);
    }

    cudaMemcpyAsync(d_out, x, (size_t)BSr * Dn * sizeof(float),
                    cudaMemcpyDeviceToDevice, 0);
}

// round 4
// speedup vs baseline: 2.0209x; 1.1052x over previous
#include <cuda_runtime.h>
#include <cuda_bf16.h>
#include <math.h>
#include <stdint.h>

// ---------------- problem constants ----------------
#define Bn   64
#define Qn   64
#define Tn   448
#define Dn   512
#define FDn  1024
#define Hn   8
#define NLn  2
#define FFn  2048
#define Sn   512           // Qn + Tn
#define DHn  64
#define BSr  (Bn*Sn)       // 32768 rows
#define BTr  (Bn*Tn)       // 28672 rows

// ---------------- scratch (device globals: allocation-free) ----------------
__device__ float g_x [BSr*Dn];
__device__ float g_q [BSr*Dn];
__device__ float g_k [BSr*Dn];
__device__ float g_v [BSr*Dn];
__device__ float g_t1[BSr*Dn];
__device__ __nv_bfloat16 g_xh[BSr*Dn],  g_xl[BSr*Dn];   // x splits (A of QKV / FFN1)
__device__ __nv_bfloat16 g_ch[BSr*Dn],  g_cl[BSr*Dn];   // ctx splits (A of Wo)
__device__ __nv_bfloat16 g_hh[BSr*FFn], g_hl[BSr*FFn];  // h splits (A of FFN2)
__device__ __nv_bfloat16 g_vh[BTr*FDn], g_vl[BTr*FDn];  // video splits
__device__ __nv_bfloat16 g_wh[Dn*FFn],  g_wl[Dn*FFn];   // weight splits (reused)

// ---------------- helpers ----------------
__device__ __forceinline__ uint32_t smem_u32(const void* p) {
    uint32_t a;
    asm("{ .reg .u64 t; cvta.to.shared.u64 t, %1; cvt.u32.u64 %0, t; }" : "=r"(a) : "l"(p));
    return a;
}
__device__ __forceinline__ void split_bf16(float x, __nv_bfloat16& h, __nv_bfloat16& l) {
    h = __float2bfloat16_rn(x);
    l = __float2bfloat16_rn(x - __bfloat162float(h));
}
__device__ __forceinline__ uint32_t pack2(__nv_bfloat16 a, __nv_bfloat16 b) {
    __nv_bfloat162 v(a, b);
    return *reinterpret_cast<uint32_t*>(&v);
}
__device__ __forceinline__ void ldsm_x4(uint32_t& r0, uint32_t& r1, uint32_t& r2, uint32_t& r3,
                                        uint32_t addr) {
    asm volatile("ldmatrix.sync.aligned.m8n8.x4.shared.b16 {%0,%1,%2,%3}, [%4];"
                 : "=r"(r0), "=r"(r1), "=r"(r2), "=r"(r3) : "r"(addr));
}
__device__ __forceinline__ void ldsm_x2t(uint32_t& r0, uint32_t& r1, uint32_t addr) {
    asm volatile("ldmatrix.sync.aligned.m8n8.x2.trans.shared.b16 {%0,%1}, [%2];"
                 : "=r"(r0), "=r"(r1) : "r"(addr));
}
__device__ __forceinline__ void mma16816(float* d, const uint32_t* a, const uint32_t* b) {
    asm volatile(
        "mma.sync.aligned.m16n8k16.row.col.f32.bf16.bf16.f32 "
        "{%0,%1,%2,%3}, {%4,%5,%6,%7}, {%8,%9}, {%0,%1,%2,%3};"
        : "+f"(d[0]), "+f"(d[1]), "+f"(d[2]), "+f"(d[3])
        : "r"(a[0]), "r"(a[1]), "r"(a[2]), "r"(a[3]), "r"(b[0]), "r"(b[1]));
}
__device__ __forceinline__ void cp16(uint32_t s, const void* g) {
    asm volatile("cp.async.cg.shared.global [%0], [%1], 16;" :: "r"(s), "l"(g));
}
#define CP_COMMIT() asm volatile("cp.async.commit_group;" ::: "memory")
#define CP_WAIT1()  asm volatile("cp.async.wait_group 1;" ::: "memory")

// ---------------- smem layout for the pipelined HMMA GEMM ----------------
#define ASTRIDE 72            // A row stride (bf16): 144B, conflict-free ldsm
#define BSTRIDE 136           // B row stride (bf16): 272B, conflict-free ldsm.trans
#define STG_A   (128 * ASTRIDE * 2)          // 18432 bytes per split
#define STG_B   (64 * BSTRIDE * 2)           // 17408 bytes per split
#define STAGE_BYTES (2 * STG_A + 2 * STG_B)  // 71680
#define NSTAGE  3
#define SM_TOTAL (NSTAGE * STAGE_BYTES)      // 215040 bytes

// ---- inner compute over one resident K-chunk (64) ----
__device__ __forceinline__ void gemm_compute(uint32_t sbase, uint32_t a_off, uint32_t b_off,
                                             float (&acc)[2][8][4])
{
#pragma unroll
    for (int ks = 0; ks < 4; ks++) {
        uint32_t ah[2][4], al[2][4];
#pragma unroll
        for (int mt = 0; mt < 2; mt++) {
            uint32_t aa = sbase + a_off + (uint32_t)(mt * 16 * ASTRIDE + ks * 16) * 2;
            ldsm_x4(ah[mt][0], ah[mt][1], ah[mt][2], ah[mt][3], aa);
            ldsm_x4(al[mt][0], al[mt][1], al[mt][2], al[mt][3], aa + STG_A);
        }
#pragma unroll
        for (int nt = 0; nt < 8; nt++) {
            uint32_t bb = sbase + 2 * STG_A + b_off + (uint32_t)(ks * 16 * BSTRIDE + nt * 8) * 2;
            uint32_t bh[2], bl[2];
            ldsm_x2t(bh[0], bh[1], bb);
            ldsm_x2t(bl[0], bl[1], bb + STG_B);
#pragma unroll
            for (int mt = 0; mt < 2; mt++) {
                mma16816(acc[mt][nt], ah[mt], bh);
                mma16816(acc[mt][nt], ah[mt], bl);
                mma16816(acc[mt][nt], al[mt], bh);
            }
        }
    }
}

// ============ pipelined bf16 HMMA GEMM: C = A @ B + bias (+epilogue) ============
// A,B pre-split bf16 hi/lo in gmem. 3-pass split (AhBh + AhBl + AlBh).
// EPI: 0=bias, 1=bias+exact GELU, 2=bias+residual.
// OUT bit0: write f32 C; OUT bit1: write bf16 split Ch/Cl.
template<int EPI, int OUT>
__global__ void __launch_bounds__(256) gemm_bf(
    const __nv_bfloat16* __restrict__ Ah, const __nv_bfloat16* __restrict__ Al,
    const __nv_bfloat16* __restrict__ Bh, const __nv_bfloat16* __restrict__ Bl,
    const float* __restrict__ bias, const float* __restrict__ R,
    float* __restrict__ C, __nv_bfloat16* __restrict__ Ch, __nv_bfloat16* __restrict__ Cl,
    int M, int N, int K)
{
    extern __shared__ char smem[];
    const uint32_t sb = smem_u32(smem);
    const int tid = threadIdx.x, wid = tid >> 5, lane = tid & 31;
    const int bx = blockIdx.x, by = blockIdx.y;
    const int warp_m = wid & 3, warp_n = wid >> 2;
    const int gid = lane >> 2, tig = lane & 3;

    // per-thread load coordinates
    const int a_row = tid >> 3, a_seg = tid & 7;     // + i*32 rows
    const int b_row = tid >> 4, b_seg = tid & 15;    // + i*16 rows

    const __nv_bfloat16* Agh = Ah + (size_t)(by * 128) * K;
    const __nv_bfloat16* Agl = Al + (size_t)(by * 128) * K;
    const __nv_bfloat16* Bgh = Bh + bx * 128;
    const __nv_bfloat16* Bgl = Bl + bx * 128;

    float acc[2][8][4];
#pragma unroll
    for (int mt = 0; mt < 2; mt++)
#pragma unroll
        for (int nt = 0; nt < 8; nt++)
#pragma unroll
            for (int e = 0; e < 4; e++) acc[mt][nt][e] = 0.f;

    const uint32_t a_off = (uint32_t)((warp_m * 32 + (lane & 15)) * ASTRIDE + (lane >> 4) * 8) * 2;
    const uint32_t b_off = (uint32_t)((lane & 15) * BSTRIDE + warp_n * 64) * 2;

    const int nch = K >> 6;

#define LOAD_STAGE(slot, kc) do { \
    const uint32_t sbase_ = sb + (slot) * STAGE_BYTES; \
    _Pragma("unroll") \
    for (int i = 0; i < 4; i++) { \
        int row = a_row + i * 32; \
        uint32_t so = sbase_ + (uint32_t)(row * ASTRIDE + a_seg * 8) * 2; \
        size_t go = (size_t)row * K + (kc) * 64 + a_seg * 8; \
        cp16(so, Agh + go); \
        cp16(so + STG_A, Agl + go); \
    } \
    _Pragma("unroll") \
    for (int i = 0; i < 4; i++) { \
        int kk = b_row + i * 16; \
        uint32_t so = sbase_ + 2 * STG_A + (uint32_t)(kk * BSTRIDE + b_seg * 8) * 2; \
        size_t go = (size_t)((kc) * 64 + kk) * N + b_seg * 8; \
        cp16(so, Bgh + go); \
        cp16(so + STG_B, Bgl + go); \
    } \
} while (0)

    LOAD_STAGE(0, 0); CP_COMMIT();
    LOAD_STAGE(1, 1); CP_COMMIT();

    for (int kc = 0; kc < nch; kc++) {
        CP_WAIT1();
        __syncthreads();
        const int nk = kc + 2;
        if (nk < nch) { LOAD_STAGE(nk % NSTAGE, nk); }
        CP_COMMIT();
        gemm_compute(sb + (kc % NSTAGE) * STAGE_BYTES, a_off, b_off, acc);
    }
#undef LOAD_STAGE

    // ---- epilogue ----
#pragma unroll
    for (int mt = 0; mt < 2; mt++) {
        const int row0 = by * 128 + warp_m * 32 + mt * 16 + gid;
#pragma unroll
        for (int nt = 0; nt < 8; nt++) {
            const int col = bx * 128 + warp_n * 64 + nt * 8 + 2 * tig;
            float2 bs = *(const float2*)(bias + col);
#pragma unroll
            for (int half = 0; half < 2; half++) {
                const int row = row0 + half * 8;
                float v0 = acc[mt][nt][half * 2 + 0] + bs.x;
                float v1 = acc[mt][nt][half * 2 + 1] + bs.y;
                if (EPI == 1) {
                    v0 = 0.5f * v0 * (1.f + erff(v0 * 0.70710678118654752f));
                    v1 = 0.5f * v1 * (1.f + erff(v1 * 0.70710678118654752f));
                } else if (EPI == 2) {
                    float2 rr = *(const float2*)(R + (size_t)row * N + col);
                    v0 += rr.x; v1 += rr.y;
                }
                if (OUT & 1) {
                    float2 o; o.x = v0; o.y = v1;
                    *(float2*)(C + (size_t)row * N + col) = o;
                }
                if (OUT & 2) {
                    __nv_bfloat16 h0, l0, h1, l1;
                    split_bf16(v0, h0, l0);
                    split_bf16(v1, h1, l1);
                    size_t off = (size_t)row * N + col;
                    *(uint32_t*)((char*)Ch + off * 2) = pack2(h0, h1);
                    *(uint32_t*)((char*)Cl + off * 2) = pack2(l0, l1);
                }
            }
        }
    }
}

// ---------------- split kernel: f32 -> bf16 hi/lo (n multiple of 1024) ----------------
__global__ void split_kernel(const float* __restrict__ in, __nv_bfloat16* __restrict__ oh,
                             __nv_bfloat16* __restrict__ ol)
{
    int i = (blockIdx.x * 256 + threadIdx.x) * 4;
    float4 a = *(const float4*)(in + i);
    __nv_bfloat16 hx, lx, hy, ly, hz, lz, hw, lw;
    split_bf16(a.x, hx, lx); split_bf16(a.y, hy, ly);
    split_bf16(a.z, hz, lz); split_bf16(a.w, hw, lw);
    *(uint2*)((char*)oh + (size_t)i * 2) = make_uint2(pack2(hx, hy), pack2(hz, hw));
    *(uint2*)((char*)ol + (size_t)i * 2) = make_uint2(pack2(lx, ly), pack2(lz, lw));
}

// ---------------- block reduction helper (128 threads = 4 warps) ----------------
__device__ __forceinline__ float blockSum128(float v, float* ws)
{
#pragma unroll
    for (int o = 16; o > 0; o >>= 1) v += __shfl_xor_sync(0xffffffffu, v, o);
    if ((threadIdx.x & 31) == 0) ws[threadIdx.x >> 5] = v;
    __syncthreads();
    v = ws[0] + ws[1] + ws[2] + ws[3];
    __syncthreads();
    return v;
}

// ---------------- LayerNorm (D=512, 128 thr/row) + split emission ----------------
__global__ void ln_kernel(const float* __restrict__ in, const float* __restrict__ gg,
                          const float* __restrict__ bb, float* __restrict__ out,
                          __nv_bfloat16* __restrict__ oh, __nv_bfloat16* __restrict__ ol,
                          int remap)
{
    __shared__ float ws[4];
    const int r = blockIdx.x;
    const float* row = in + (size_t)r * Dn;
    const int orow = remap ? ((r / Tn) * Sn + Qn + (r % Tn)) : r;
    const int t = threadIdx.x;
    float val[4]; float s = 0.f;
#pragma unroll
    for (int i = 0; i < 4; i++) { val[i] = row[t + i * 128]; s += val[i]; }
    s = blockSum128(s, ws);
    const float mean = s * (1.0f / Dn);
    float vs = 0.f;
#pragma unroll
    for (int i = 0; i < 4; i++) { float d = val[i] - mean; vs += d * d; }
    vs = blockSum128(vs, ws);
    const float rstd = rsqrtf(vs * (1.0f / Dn) + 1e-12f);
    const size_t ob = (size_t)orow * Dn;
#pragma unroll
    for (int i = 0; i < 4; i++) {
        int c = t + i * 128;
        float o = (val[i] - mean) * rstd * gg[c] + bb[c];
        out[ob + c] = o;
        __nv_bfloat16 hh, ll;
        split_bf16(o, hh, ll);
        oh[ob + c] = hh;
        ol[ob + c] = ll;
    }
}

// ---------------- embed: concat + pos + mod, LN, split emission ----------------
__global__ void embed_ln_kernel(const float* __restrict__ question,
                                const float* __restrict__ pos, const float* __restrict__ mod,
                                const float* __restrict__ gg, const float* __restrict__ bb,
                                float* __restrict__ x,
                                __nv_bfloat16* __restrict__ oh, __nv_bfloat16* __restrict__ ol)
{
    __shared__ float ws[4];
    const int row = blockIdx.x;
    const int s = row % Sn, b = row / Sn;
    const int t = threadIdx.x;
    const float* base = (s < Qn) ? (question + (size_t)(b * Qn + s) * Dn)
                                 : (x + (size_t)row * Dn);
    const float* pe = pos + (size_t)s * Dn;
    const float* me = mod + (s >= Qn ? Dn : 0);
    float val[4]; float sum = 0.f;
#pragma unroll
    for (int i = 0; i < 4; i++) {
        int c = t + i * 128;
        val[i] = base[c] + pe[c] + me[c];
        sum += val[i];
    }
    sum = blockSum128(sum, ws);
    const float mean = sum * (1.0f / Dn);
    float vs = 0.f;
#pragma unroll
    for (int i = 0; i < 4; i++) { float d = val[i] - mean; vs += d * d; }
    vs = blockSum128(vs, ws);
    const float rstd = rsqrtf(vs * (1.0f / Dn) + 1e-12f);
    const size_t ob = (size_t)row * Dn;
#pragma unroll
    for (int i = 0; i < 4; i++) {
        int c = t + i * 128;
        float o = (val[i] - mean) * rstd * gg[c] + bb[c];
        x[ob + c] = o;
        __nv_bfloat16 hh, ll;
        split_bf16(o, hh, ll);
        oh[ob + c] = hh;
        ol[ob + c] = ll;
    }
}

// ---------------- flash-style attention: 64-query tile, split output ----------------
#define ATTN_SMEM_FLOATS (4 * 64 * 65 + 4 * 64)
#define ATTN_SMEM_BYTES  (ATTN_SMEM_FLOATS * 4)

__global__ void __launch_bounds__(256) attn_kernel(
    const float* __restrict__ q, const float* __restrict__ k, const float* __restrict__ v,
    const int* __restrict__ mask,
    __nv_bfloat16* __restrict__ ctxh, __nv_bfloat16* __restrict__ ctxl)
{
    extern __shared__ float sm[];
    float* Qs    = sm;
    float* Ks    = Qs + 64 * 65;
    float* Vs    = Ks + 64 * 65;
    float* Ps    = Vs + 64 * 65;
    float* mrow  = Ps + 64 * 65;
    float* lrow  = mrow + 64;
    float* scl   = lrow + 64;
    float* maskb = scl + 64;

    const int tid = threadIdx.x;
    const int qt = blockIdx.x;
    const int bh = blockIdx.y;
    const int b = bh >> 3, h = bh & 7;
    const int ty = tid >> 4, tx = tid & 15;
    const int srow = tid >> 2, ssub = tid & 3;     // softmax: 4 threads per row

    {
        const int c = (tid & 15) * 4;
        for (int r = tid >> 4; r < 64; r += 16) {
            const float* src = q + (size_t)(b * Sn + qt * 64 + r) * Dn + h * DHn + c;
            float4 a = *(const float4*)src;
            Qs[r * 65 + c + 0] = a.x * 0.125f;
            Qs[r * 65 + c + 1] = a.y * 0.125f;
            Qs[r * 65 + c + 2] = a.z * 0.125f;
            Qs[r * 65 + c + 3] = a.w * 0.125f;
        }
    }
    if (tid < 64) { mrow[tid] = -1e30f; lrow[tid] = 0.f; }

    float o[4][4];
#pragma unroll
    for (int i = 0; i < 4; i++)
#pragma unroll
        for (int j = 0; j < 4; j++) o[i][j] = 0.f;

    for (int kt = 0; kt < Sn / 64; kt++) {
        {
            const int c = (tid & 15) * 4;
            for (int r = tid >> 4; r < 64; r += 16) {
                const size_t goff = (size_t)(b * Sn + kt * 64 + r) * Dn + h * DHn + c;
                float4 a = *(const float4*)(k + goff);
                Ks[r * 65 + c + 0] = a.x; Ks[r * 65 + c + 1] = a.y;
                Ks[r * 65 + c + 2] = a.z; Ks[r * 65 + c + 3] = a.w;
                float4 vv = *(const float4*)(v + goff);
                Vs[r * 65 + c + 0] = vv.x; Vs[r * 65 + c + 1] = vv.y;
                Vs[r * 65 + c + 2] = vv.z; Vs[r * 65 + c + 3] = vv.w;
            }
            if (tid < 64)
                maskb[tid] = (mask[b * Sn + kt * 64 + tid] == 0) ? -1e30f : 0.f;
        }
        __syncthreads();

        // S tile = Qs @ Ks^T (+ mask bias)
        {
            float sreg[4][4];
#pragma unroll
            for (int i = 0; i < 4; i++)
#pragma unroll
                for (int j = 0; j < 4; j++) sreg[i][j] = 0.f;
#pragma unroll 8
            for (int d = 0; d < 64; d++) {
                float ar[4], br[4];
#pragma unroll
                for (int i = 0; i < 4; i++) ar[i] = Qs[(ty * 4 + i) * 65 + d];
#pragma unroll
                for (int j = 0; j < 4; j++) br[j] = Ks[(tx * 4 + j) * 65 + d];
#pragma unroll
                for (int i = 0; i < 4; i++)
#pragma unroll
                    for (int j = 0; j < 4; j++) sreg[i][j] = fmaf(ar[i], br[j], sreg[i][j]);
            }
#pragma unroll
            for (int i = 0; i < 4; i++)
#pragma unroll
                for (int j = 0; j < 4; j++)
                    Ps[(ty * 4 + i) * 65 + tx * 4 + j] = sreg[i][j] + maskb[tx * 4 + j];
        }
        __syncthreads();

        // online softmax: 4 threads per query row
        {
            float* prow = Ps + srow * 65 + ssub * 16;
            float mold = mrow[srow];
            float tmax = -1e30f;
#pragma unroll
            for (int j = 0; j < 16; j++) tmax = fmaxf(tmax, prow[j]);
            tmax = fmaxf(tmax, __shfl_xor_sync(0xffffffffu, tmax, 1));
            tmax = fmaxf(tmax, __shfl_xor_sync(0xffffffffu, tmax, 2));
            float mnew = fmaxf(mold, tmax);
            float f = __expf(mold - mnew);
            float ls = 0.f;
#pragma unroll
            for (int j = 0; j < 16; j++) {
                float p = __expf(prow[j] - mnew);
                prow[j] = p;
                ls += p;
            }
            ls += __shfl_xor_sync(0xffffffffu, ls, 1);
            ls += __shfl_xor_sync(0xffffffffu, ls, 2);
            if (ssub == 0) {
                lrow[srow] = lrow[srow] * f + ls;
                mrow[srow] = mnew;
                scl[srow] = f;
            }
        }
        __syncthreads();

        // O = O*f + P @ V
        {
#pragma unroll
            for (int i = 0; i < 4; i++) {
                float f = scl[ty * 4 + i];
#pragma unroll
                for (int j = 0; j < 4; j++) o[i][j] *= f;
            }
#pragma unroll 8
            for (int kc = 0; kc < 64; kc++) {
                float pr[4], vr[4];
#pragma unroll
                for (int i = 0; i < 4; i++) pr[i] = Ps[(ty * 4 + i) * 65 + kc];
#pragma unroll
                for (int j = 0; j < 4; j++) vr[j] = Vs[kc * 65 + tx * 4 + j];
#pragma unroll
                for (int i = 0; i < 4; i++)
#pragma unroll
                    for (int j = 0; j < 4; j++) o[i][j] = fmaf(pr[i], vr[j], o[i][j]);
            }
        }
        __syncthreads();
    }

    // write ctx as bf16 hi/lo splits (only consumer is the Wo GEMM)
#pragma unroll
    for (int i = 0; i < 4; i++) {
        const int qr = ty * 4 + i;
        const float inv = 1.0f / lrow[qr];
        float e0 = o[i][0] * inv, e1 = o[i][1] * inv;
        float e2 = o[i][2] * inv, e3 = o[i][3] * inv;
        __nv_bfloat16 h0, l0, h1, l1, h2, l2, h3, l3;
        split_bf16(e0, h0, l0); split_bf16(e1, h1, l1);
        split_bf16(e2, h2, l2); split_bf16(e3, h3, l3);
        size_t off = (size_t)(b * Sn + qt * 64 + qr) * Dn + h * DHn + tx * 4;
        *(uint2*)((char*)ctxh + off * 2) = make_uint2(pack2(h0, h1), pack2(h2, h3));
        *(uint2*)((char*)ctxl + off * 2) = make_uint2(pack2(l0, l1), pack2(l2, l3));
    }
}

// ---------------- host orchestration ----------------
extern "C" void kernel_launch(void* const* d_in, const int* in_sizes, int n_in,
                              void* d_out, int out_size)
{
    const float* video    = (const float*)d_in[0];
    const float* question = (const float*)d_in[1];
    const int*   mask     = (const int*)  d_in[2];
    const float* pos_emb  = (const float*)d_in[3];
    const float* mod_emb  = (const float*)d_in[4];
    const float* Wv       = (const float*)d_in[5];
    const float* bv       = (const float*)d_in[6];
    const float* nv_g     = (const float*)d_in[7];
    const float* nv_b     = (const float*)d_in[8];
    const float* emb_g    = (const float*)d_in[9];
    const float* emb_b    = (const float*)d_in[10];
    const float* Wq       = (const float*)d_in[11];
    const float* bq       = (const float*)d_in[12];
    const float* Wk       = (const float*)d_in[13];
    const float* bk       = (const float*)d_in[14];
    const float* Wva      = (const float*)d_in[15];
    const float* bva      = (const float*)d_in[16];
    const float* Wo       = (const float*)d_in[17];
    const float* bo       = (const float*)d_in[18];
    const float* ln1_g    = (const float*)d_in[19];
    const float* ln1_b    = (const float*)d_in[20];
    const float* W1       = (const float*)d_in[21];
    const float* b1       = (const float*)d_in[22];
    const float* W2       = (const float*)d_in[23];
    const float* b2       = (const float*)d_in[24];
    const float* ln2_g    = (const float*)d_in[25];
    const float* ln2_b    = (const float*)d_in[26];

    float *x, *q, *k, *v, *t1;
    __nv_bfloat16 *xh, *xl, *ch, *cl, *hh, *hl, *vh, *vl, *wh, *wl;
    cudaGetSymbolAddress((void**)&x,  g_x);
    cudaGetSymbolAddress((void**)&q,  g_q);
    cudaGetSymbolAddress((void**)&k,  g_k);
    cudaGetSymbolAddress((void**)&v,  g_v);
    cudaGetSymbolAddress((void**)&t1, g_t1);
    cudaGetSymbolAddress((void**)&xh, g_xh); cudaGetSymbolAddress((void**)&xl, g_xl);
    cudaGetSymbolAddress((void**)&ch, g_ch); cudaGetSymbolAddress((void**)&cl, g_cl);
    cudaGetSymbolAddress((void**)&hh, g_hh); cudaGetSymbolAddress((void**)&hl, g_hl);
    cudaGetSymbolAddress((void**)&vh, g_vh); cudaGetSymbolAddress((void**)&vl, g_vl);
    cudaGetSymbolAddress((void**)&wh, g_wh); cudaGetSymbolAddress((void**)&wl, g_wl);

    static bool attr_set = false;
    if (!attr_set) {
        cudaFuncSetAttribute(attn_kernel, cudaFuncAttributeMaxDynamicSharedMemorySize,
                             ATTN_SMEM_BYTES);
        cudaFuncSetAttribute(gemm_bf<0,1>, cudaFuncAttributeMaxDynamicSharedMemorySize, SM_TOTAL);
        cudaFuncSetAttribute(gemm_bf<1,2>, cudaFuncAttributeMaxDynamicSharedMemorySize, SM_TOTAL);
        cudaFuncSetAttribute(gemm_bf<2,1>, cudaFuncAttributeMaxDynamicSharedMemorySize, SM_TOTAL);
        attr_set = true;
    }

    // one-shot input splits: video + Wv
    split_kernel<<<(BTr * FDn) / 1024, 256>>>(video, vh, vl);
    split_kernel<<<(FDn * Dn) / 1024, 256>>>(Wv, wh, wl);
    // 1) video projection
    gemm_bf<0,1><<<dim3(Dn / 128, BTr / 128), 256, SM_TOTAL>>>(
        vh, vl, wh, wl, bv, nullptr, t1, nullptr, nullptr, BTr, Dn, FDn);
    // 2) LN(video) into x rows [b*S + Q + t] (+ splits, overwritten by embed_ln)
    ln_kernel<<<BTr, 128>>>(t1, nv_g, nv_b, x, xh, xl, 1);
    // 3) concat + pos/mod emb + LN -> x (+ splits)
    embed_ln_kernel<<<BSr, 128>>>(question, pos_emb, mod_emb, emb_g, emb_b, x, xh, xl);

    for (int i = 0; i < NLn; i++) {
        const size_t wD = (size_t)i * Dn * Dn;
        split_kernel<<<(Dn * Dn) / 1024, 256>>>(Wq + wD, wh, wl);
        gemm_bf<0,1><<<dim3(Dn / 128, BSr / 128), 256, SM_TOTAL>>>(
            xh, xl, wh, wl, bq + i * Dn, nullptr, q, nullptr, nullptr, BSr, Dn, Dn);
        split_kernel<<<(Dn * Dn) / 1024, 256>>>(Wk + wD, wh, wl);
        gemm_bf<0,1><<<dim3(Dn / 128, BSr / 128), 256, SM_TOTAL>>>(
            xh, xl, wh, wl, bk + i * Dn, nullptr, k, nullptr, nullptr, BSr, Dn, Dn);
        split_kernel<<<(Dn * Dn) / 1024, 256>>>(Wva + wD, wh, wl);
        gemm_bf<0,1><<<dim3(Dn / 128, BSr / 128), 256, SM_TOTAL>>>(
            xh, xl, wh, wl, bva + i * Dn, nullptr, v, nullptr, nullptr, BSr, Dn, Dn);

        attn_kernel<<<dim3(Sn / 64, Bn * Hn), 256, ATTN_SMEM_BYTES>>>(q, k, v, mask, ch, cl);

        split_kernel<<<(Dn * Dn) / 1024, 256>>>(Wo + wD, wh, wl);
        gemm_bf<2,1><<<dim3(Dn / 128, BSr / 128), 256, SM_TOTAL>>>(
            ch, cl, wh, wl, bo + i * Dn, x, t1, nullptr, nullptr, BSr, Dn, Dn);
        ln_kernel<<<BSr, 128>>>(t1, ln1_g + i * Dn, ln1_b + i * Dn, x, xh, xl, 0);

        split_kernel<<<(Dn * FFn) / 1024, 256>>>(W1 + (size_t)i * Dn * FFn, wh, wl);
        gemm_bf<1,2><<<dim3(FFn / 128, BSr / 128), 256, SM_TOTAL>>>(
            xh, xl, wh, wl, b1 + i * FFn, nullptr, nullptr, hh, hl, BSr, FFn, Dn);
        split_kernel<<<(FFn * Dn) / 1024, 256>>>(W2 + (size_t)i * FFn * Dn, wh, wl);
        gemm_bf<2,1><<<dim3(Dn / 128, BSr / 128), 256, SM_TOTAL>>>(
            hh, hl, wh, wl, b2 + i * Dn, x, t1, nullptr, nullptr, BSr, Dn, FFn);
        ln_kernel<<<BSr, 128>>>(t1, ln2_g + i * Dn, ln2_b + i * Dn, x, xh, xl, 0);
    }

    cudaMemcpyAsync(d_out, x, (size_t)BSr * Dn * sizeof(float),
                    cudaMemcpyDeviceToDevice, 0);
}

// round 5
// speedup vs baseline: 2.5131x; 1.2435x over previous
#include <cuda_runtime.h>
#include <cuda_bf16.h>
#include <math.h>
#include <stdint.h>

// ---------------- problem constants ----------------
#define Bn   64
#define Qn   64
#define Tn   448
#define Dn   512
#define FDn  1024
#define Hn   8
#define NLn  2
#define FFn  2048
#define Sn   512           // Qn + Tn
#define DHn  64
#define BSr  (Bn*Sn)       // 32768 rows
#define BTr  (Bn*Tn)       // 28672 rows

// ---------------- scratch (device globals: allocation-free) ----------------
__device__ float g_x [BSr*Dn];
__device__ float g_t1[BSr*Dn];
__device__ __nv_bfloat16 g_xh [BSr*Dn],  g_xl [BSr*Dn];   // x splits
__device__ __nv_bfloat16 g_aqh[BSr*Dn],  g_aql[BSr*Dn];   // q splits
__device__ __nv_bfloat16 g_akh[BSr*Dn],  g_akl[BSr*Dn];   // k splits
__device__ __nv_bfloat16 g_avh[BSr*Dn],  g_avl[BSr*Dn];   // v splits
__device__ __nv_bfloat16 g_ch [BSr*Dn],  g_cl [BSr*Dn];   // ctx splits
__device__ __nv_bfloat16 g_hh [BSr*FFn], g_hl [BSr*FFn];  // ffn h splits
__device__ __nv_bfloat16 g_vh [BTr*FDn], g_vl [BTr*FDn];  // video splits
__device__ __nv_bfloat16 g_wh [Dn*FFn],  g_wl [Dn*FFn];   // weight splits (reused)

// ---------------- helpers ----------------
__device__ __forceinline__ uint32_t smem_u32(const void* p) {
    uint32_t a;
    asm("{ .reg .u64 t; cvta.to.shared.u64 t, %1; cvt.u32.u64 %0, t; }" : "=r"(a) : "l"(p));
    return a;
}
__device__ __forceinline__ void split_bf16(float x, __nv_bfloat16& h, __nv_bfloat16& l) {
    h = __float2bfloat16_rn(x);
    l = __float2bfloat16_rn(x - __bfloat162float(h));
}
__device__ __forceinline__ uint32_t pack2(__nv_bfloat16 a, __nv_bfloat16 b) {
    __nv_bfloat162 v(a, b);
    return *reinterpret_cast<uint32_t*>(&v);
}
__device__ __forceinline__ void ldsm_x4(uint32_t& r0, uint32_t& r1, uint32_t& r2, uint32_t& r3,
                                        uint32_t addr) {
    asm volatile("ldmatrix.sync.aligned.m8n8.x4.shared.b16 {%0,%1,%2,%3}, [%4];"
                 : "=r"(r0), "=r"(r1), "=r"(r2), "=r"(r3) : "r"(addr));
}
__device__ __forceinline__ void ldsm_x2t(uint32_t& r0, uint32_t& r1, uint32_t addr) {
    asm volatile("ldmatrix.sync.aligned.m8n8.x2.trans.shared.b16 {%0,%1}, [%2];"
                 : "=r"(r0), "=r"(r1) : "r"(addr));
}
__device__ __forceinline__ void ldsm_x4t(uint32_t& r0, uint32_t& r1, uint32_t& r2, uint32_t& r3,
                                         uint32_t addr) {
    asm volatile("ldmatrix.sync.aligned.m8n8.x4.trans.shared.b16 {%0,%1,%2,%3}, [%4];"
                 : "=r"(r0), "=r"(r1), "=r"(r2), "=r"(r3) : "r"(addr));
}
__device__ __forceinline__ void mma16816(float* d, const uint32_t* a, const uint32_t* b) {
    asm volatile(
        "mma.sync.aligned.m16n8k16.row.col.f32.bf16.bf16.f32 "
        "{%0,%1,%2,%3}, {%4,%5,%6,%7}, {%8,%9}, {%0,%1,%2,%3};"
        : "+f"(d[0]), "+f"(d[1]), "+f"(d[2]), "+f"(d[3])
        : "r"(a[0]), "r"(a[1]), "r"(a[2]), "r"(a[3]), "r"(b[0]), "r"(b[1]));
}
__device__ __forceinline__ void cp16(uint32_t s, const void* g) {
    asm volatile("cp.async.cg.shared.global [%0], [%1], 16;" :: "r"(s), "l"(g));
}
#define CP_COMMIT() asm volatile("cp.async.commit_group;" ::: "memory")
#define CP_WAIT1()  asm volatile("cp.async.wait_group 1;" ::: "memory")

// fast base-2 exp on the FMA pipe (no MUFU). Valid for y <= ~126; clamps below.
__device__ __forceinline__ float fexp2(float y) {
    y = fmaxf(y, -126.f);
    float n = rintf(y);
    float r = y - n;
    float p = fmaf(1.333356e-3f, r, 9.618129e-3f);
    p = fmaf(p, r, 5.5504109e-2f);
    p = fmaf(p, r, 2.40226507e-1f);
    p = fmaf(p, r, 6.93147181e-1f);
    p = fmaf(p, r, 1.0f);
    return p * __int_as_float(((int)n + 127) << 23);
}

// ---------------- smem layout for the pipelined HMMA GEMM ----------------
#define ASTRIDE 72            // A row stride (bf16): 144B, conflict-free ldsm
#define BSTRIDE 136           // B row stride (bf16): 272B, conflict-free ldsm.trans
#define STG_A   (128 * ASTRIDE * 2)          // 18432 bytes per split
#define STG_B   (64 * BSTRIDE * 2)           // 17408 bytes per split
#define STAGE_BYTES (2 * STG_A + 2 * STG_B)  // 71680
#define NSTAGE  3
#define SM_TOTAL (NSTAGE * STAGE_BYTES)      // 215040 bytes

// ---- inner compute over one resident K-chunk (64) ----
__device__ __forceinline__ void gemm_compute(uint32_t sbase, uint32_t a_off, uint32_t b_off,
                                             float (&acc)[2][8][4])
{
#pragma unroll
    for (int ks = 0; ks < 4; ks++) {
        uint32_t ah[2][4], al[2][4];
#pragma unroll
        for (int mt = 0; mt < 2; mt++) {
            uint32_t aa = sbase + a_off + (uint32_t)(mt * 16 * ASTRIDE + ks * 16) * 2;
            ldsm_x4(ah[mt][0], ah[mt][1], ah[mt][2], ah[mt][3], aa);
            ldsm_x4(al[mt][0], al[mt][1], al[mt][2], al[mt][3], aa + STG_A);
        }
#pragma unroll
        for (int nt = 0; nt < 8; nt++) {
            uint32_t bb = sbase + 2 * STG_A + b_off + (uint32_t)(ks * 16 * BSTRIDE + nt * 8) * 2;
            uint32_t bh[2], bl[2];
            ldsm_x2t(bh[0], bh[1], bb);
            ldsm_x2t(bl[0], bl[1], bb + STG_B);
#pragma unroll
            for (int mt = 0; mt < 2; mt++) {
                mma16816(acc[mt][nt], ah[mt], bh);
                mma16816(acc[mt][nt], ah[mt], bl);
                mma16816(acc[mt][nt], al[mt], bh);
            }
        }
    }
}

// ============ pipelined bf16 HMMA GEMM: C = A @ B + bias (+epilogue) ============
// EPI: 0=bias, 1=bias+exact GELU, 2=bias+residual.
// OUT bit0: write f32 C; OUT bit1: write bf16 split Ch/Cl.
template<int EPI, int OUT>
__global__ void __launch_bounds__(256) gemm_bf(
    const __nv_bfloat16* __restrict__ Ah, const __nv_bfloat16* __restrict__ Al,
    const __nv_bfloat16* __restrict__ Bh, const __nv_bfloat16* __restrict__ Bl,
    const float* __restrict__ bias, const float* __restrict__ R,
    float* __restrict__ C, __nv_bfloat16* __restrict__ Ch, __nv_bfloat16* __restrict__ Cl,
    int M, int N, int K)
{
    extern __shared__ char smem[];
    const uint32_t sb = smem_u32(smem);
    const int tid = threadIdx.x, wid = tid >> 5, lane = tid & 31;
    const int bx = blockIdx.x, by = blockIdx.y;
    const int warp_m = wid & 3, warp_n = wid >> 2;
    const int gid = lane >> 2, tig = lane & 3;

    const int a_row = tid >> 3, a_seg = tid & 7;
    const int b_row = tid >> 4, b_seg = tid & 15;

    const __nv_bfloat16* Agh = Ah + (size_t)(by * 128) * K;
    const __nv_bfloat16* Agl = Al + (size_t)(by * 128) * K;
    const __nv_bfloat16* Bgh = Bh + bx * 128;
    const __nv_bfloat16* Bgl = Bl + bx * 128;

    float acc[2][8][4];
#pragma unroll
    for (int mt = 0; mt < 2; mt++)
#pragma unroll
        for (int nt = 0; nt < 8; nt++)
#pragma unroll
            for (int e = 0; e < 4; e++) acc[mt][nt][e] = 0.f;

    const uint32_t a_off = (uint32_t)((warp_m * 32 + (lane & 15)) * ASTRIDE + (lane >> 4) * 8) * 2;
    const uint32_t b_off = (uint32_t)((lane & 15) * BSTRIDE + warp_n * 64) * 2;

    const int nch = K >> 6;

#define LOAD_STAGE(slot, kc) do { \
    const uint32_t sbase_ = sb + (slot) * STAGE_BYTES; \
    _Pragma("unroll") \
    for (int i = 0; i < 4; i++) { \
        int row = a_row + i * 32; \
        uint32_t so = sbase_ + (uint32_t)(row * ASTRIDE + a_seg * 8) * 2; \
        size_t go = (size_t)row * K + (kc) * 64 + a_seg * 8; \
        cp16(so, Agh + go); \
        cp16(so + STG_A, Agl + go); \
    } \
    _Pragma("unroll") \
    for (int i = 0; i < 4; i++) { \
        int kk = b_row + i * 16; \
        uint32_t so = sbase_ + 2 * STG_A + (uint32_t)(kk * BSTRIDE + b_seg * 8) * 2; \
        size_t go = (size_t)((kc) * 64 + kk) * N + b_seg * 8; \
        cp16(so, Bgh + go); \
        cp16(so + STG_B, Bgl + go); \
    } \
} while (0)

    LOAD_STAGE(0, 0); CP_COMMIT();
    LOAD_STAGE(1, 1); CP_COMMIT();

    for (int kc = 0; kc < nch; kc++) {
        CP_WAIT1();
        __syncthreads();
        const int nk = kc + 2;
        if (nk < nch) { LOAD_STAGE(nk % NSTAGE, nk); }
        CP_COMMIT();
        gemm_compute(sb + (kc % NSTAGE) * STAGE_BYTES, a_off, b_off, acc);
    }
#undef LOAD_STAGE

    // ---- epilogue ----
#pragma unroll
    for (int mt = 0; mt < 2; mt++) {
        const int row0 = by * 128 + warp_m * 32 + mt * 16 + gid;
#pragma unroll
        for (int nt = 0; nt < 8; nt++) {
            const int col = bx * 128 + warp_n * 64 + nt * 8 + 2 * tig;
            float2 bs = *(const float2*)(bias + col);
#pragma unroll
            for (int half = 0; half < 2; half++) {
                const int row = row0 + half * 8;
                float v0 = acc[mt][nt][half * 2 + 0] + bs.x;
                float v1 = acc[mt][nt][half * 2 + 1] + bs.y;
                if (EPI == 1) {
                    v0 = 0.5f * v0 * (1.f + erff(v0 * 0.70710678118654752f));
                    v1 = 0.5f * v1 * (1.f + erff(v1 * 0.70710678118654752f));
                } else if (EPI == 2) {
                    float2 rr = *(const float2*)(R + (size_t)row * N + col);
                    v0 += rr.x; v1 += rr.y;
                }
                if (OUT & 1) {
                    float2 o; o.x = v0; o.y = v1;
                    *(float2*)(C + (size_t)row * N + col) = o;
                }
                if (OUT & 2) {
                    __nv_bfloat16 h0, l0, h1, l1;
                    split_bf16(v0, h0, l0);
                    split_bf16(v1, h1, l1);
                    size_t off = (size_t)row * N + col;
                    *(uint32_t*)((char*)Ch + off * 2) = pack2(h0, h1);
                    *(uint32_t*)((char*)Cl + off * 2) = pack2(l0, l1);
                }
            }
        }
    }
}

// ---------------- split kernel: f32 -> bf16 hi/lo ----------------
__global__ void split_kernel(const float* __restrict__ in, __nv_bfloat16* __restrict__ oh,
                             __nv_bfloat16* __restrict__ ol)
{
    int i = (blockIdx.x * 256 + threadIdx.x) * 4;
    float4 a = *(const float4*)(in + i);
    __nv_bfloat16 hx, lx, hy, ly, hz, lz, hw, lw;
    split_bf16(a.x, hx, lx); split_bf16(a.y, hy, ly);
    split_bf16(a.z, hz, lz); split_bf16(a.w, hw, lw);
    *(uint2*)((char*)oh + (size_t)i * 2) = make_uint2(pack2(hx, hy), pack2(hz, hw));
    *(uint2*)((char*)ol + (size_t)i * 2) = make_uint2(pack2(lx, ly), pack2(lz, lw));
}

// ---------------- block reduction helper (128 threads = 4 warps) ----------------
__device__ __forceinline__ float blockSum128(float v, float* ws)
{
#pragma unroll
    for (int o = 16; o > 0; o >>= 1) v += __shfl_xor_sync(0xffffffffu, v, o);
    if ((threadIdx.x & 31) == 0) ws[threadIdx.x >> 5] = v;
    __syncthreads();
    v = ws[0] + ws[1] + ws[2] + ws[3];
    __syncthreads();
    return v;
}

// ---------------- LayerNorm (D=512, 128 thr/row) + split emission ----------------
__global__ void ln_kernel(const float* __restrict__ in, const float* __restrict__ gg,
                          const float* __restrict__ bb, float* __restrict__ out,
                          __nv_bfloat16* __restrict__ oh, __nv_bfloat16* __restrict__ ol,
                          int remap)
{
    __shared__ float ws[4];
    const int r = blockIdx.x;
    const float* row = in + (size_t)r * Dn;
    const int orow = remap ? ((r / Tn) * Sn + Qn + (r % Tn)) : r;
    const int t = threadIdx.x;
    float val[4]; float s = 0.f;
#pragma unroll
    for (int i = 0; i < 4; i++) { val[i] = row[t + i * 128]; s += val[i]; }
    s = blockSum128(s, ws);
    const float mean = s * (1.0f / Dn);
    float vs = 0.f;
#pragma unroll
    for (int i = 0; i < 4; i++) { float d = val[i] - mean; vs += d * d; }
    vs = blockSum128(vs, ws);
    const float rstd = rsqrtf(vs * (1.0f / Dn) + 1e-12f);
    const size_t ob = (size_t)orow * Dn;
#pragma unroll
    for (int i = 0; i < 4; i++) {
        int c = t + i * 128;
        float o = (val[i] - mean) * rstd * gg[c] + bb[c];
        out[ob + c] = o;
        __nv_bfloat16 hh, ll;
        split_bf16(o, hh, ll);
        oh[ob + c] = hh;
        ol[ob + c] = ll;
    }
}

// ---------------- embed: concat + pos + mod, LN, split emission ----------------
__global__ void embed_ln_kernel(const float* __restrict__ question,
                                const float* __restrict__ pos, const float* __restrict__ mod,
                                const float* __restrict__ gg, const float* __restrict__ bb,
                                float* __restrict__ x,
                                __nv_bfloat16* __restrict__ oh, __nv_bfloat16* __restrict__ ol)
{
    __shared__ float ws[4];
    const int row = blockIdx.x;
    const int s = row % Sn, b = row / Sn;
    const int t = threadIdx.x;
    const float* base = (s < Qn) ? (question + (size_t)(b * Qn + s) * Dn)
                                 : (x + (size_t)row * Dn);
    const float* pe = pos + (size_t)s * Dn;
    const float* me = mod + (s >= Qn ? Dn : 0);
    float val[4]; float sum = 0.f;
#pragma unroll
    for (int i = 0; i < 4; i++) {
        int c = t + i * 128;
        val[i] = base[c] + pe[c] + me[c];
        sum += val[i];
    }
    sum = blockSum128(sum, ws);
    const float mean = sum * (1.0f / Dn);
    float vs = 0.f;
#pragma unroll
    for (int i = 0; i < 4; i++) { float d = val[i] - mean; vs += d * d; }
    vs = blockSum128(vs, ws);
    const float rstd = rsqrtf(vs * (1.0f / Dn) + 1e-12f);
    const size_t ob = (size_t)row * Dn;
#pragma unroll
    for (int i = 0; i < 4; i++) {
        int c = t + i * 128;
        float o = (val[i] - mean) * rstd * gg[c] + bb[c];
        x[ob + c] = o;
        __nv_bfloat16 hh, ll;
        split_bf16(o, hh, ll);
        oh[ob + c] = hh;
        ol[ob + c] = ll;
    }
}

// ================ HMMA flash attention =================
// Block: 64 queries x full S keys (8 tiles of 64), one (b,h). 8 warps.
// warp_q = wid&3 (16 q-rows), warp_n = wid>>2 (32-key half for QK / 32-dh half for PV).
// 3-pass bf16 split on both QK^T and PV. Softmax in base-2 via fexp2 (FMA pipe).
#define AT_QH  0
#define AT_QL  (AT_QH + 9216)
#define AT_KH  (AT_QL + 9216)
#define AT_KL  (AT_KH + 9216)
#define AT_VH  (AT_KL + 9216)
#define AT_VL  (AT_VH + 9216)
#define AT_PS  (AT_VL + 9216)           // f32 [64][68]
#define AT_PBH (AT_PS + 17408)
#define AT_PBL (AT_PBH + 9216)
#define AT_MR  (AT_PBL + 9216)
#define AT_LR  (AT_MR + 256)
#define AT_SC  (AT_LR + 256)
#define AT_MB  (AT_SC + 256)
#define AT_TOTAL (AT_MB + 256)          // 92160 bytes -> 2 CTAs/SM

#define SC2 0.18033688f                 // 0.125 * log2(e)

__global__ void __launch_bounds__(256, 2) attn_kernel(
    const __nv_bfloat16* __restrict__ qh, const __nv_bfloat16* __restrict__ ql,
    const __nv_bfloat16* __restrict__ kh, const __nv_bfloat16* __restrict__ kl,
    const __nv_bfloat16* __restrict__ vh, const __nv_bfloat16* __restrict__ vl,
    const int* __restrict__ mask,
    __nv_bfloat16* __restrict__ ctxh, __nv_bfloat16* __restrict__ ctxl)
{
    extern __shared__ char smem[];
    const uint32_t sb = smem_u32(smem);
    float* Ps    = (float*)(smem + AT_PS);
    float* mrow  = (float*)(smem + AT_MR);
    float* lrow  = (float*)(smem + AT_LR);
    float* scl   = (float*)(smem + AT_SC);
    float* maskb = (float*)(smem + AT_MB);

    const int tid = threadIdx.x, wid = tid >> 5, lane = tid & 31;
    const int warp_q = wid & 3, warp_n = wid >> 2;
    const int gid = lane >> 2, tig = lane & 3;
    const int qt = blockIdx.x, bh_ = blockIdx.y;
    const int b = bh_ >> 3, h = bh_ & 7;
    const size_t rowbase = (size_t)(b * Sn + qt * 64);

    // load Q tiles (64x64 bf16 hi/lo)
#pragma unroll
    for (int it = 0; it < 2; it++) {
        int idx = tid + it * 256;
        int r = idx >> 3, c8 = (idx & 7) * 8;
        size_t go = (rowbase + r) * Dn + h * DHn + c8;
        *(uint4*)(smem + AT_QH + (r * 72 + c8) * 2) = *(const uint4*)(qh + go);
        *(uint4*)(smem + AT_QL + (r * 72 + c8) * 2) = *(const uint4*)(ql + go);
    }
    if (tid < 64) { mrow[tid] = -1e30f; lrow[tid] = 0.f; }

    float o[4][4];
#pragma unroll
    for (int nt = 0; nt < 4; nt++)
#pragma unroll
        for (int e = 0; e < 4; e++) o[nt][e] = 0.f;

    // fragment address building blocks
    const uint32_t aqb = ((uint32_t)((warp_q * 16 + (lane & 15)) * 72 + (lane >> 4) * 8)) * 2;
    const uint32_t n_add = (lane & 7) + ((lane >> 4) << 3);   // K non-trans x4
    const uint32_t k_add = ((lane >> 3) & 1) * 8;
    const int srow = tid >> 2, ssub = tid & 3;

    for (int kt = 0; kt < 8; kt++) {
        __syncthreads();   // prior PV done before K/V overwrite
        // ---- load K/V tile (64 keys x 64 dh, hi/lo) ----
#pragma unroll
        for (int it = 0; it < 2; it++) {
            int idx = tid + it * 256;
            int r = idx >> 3, c8 = (idx & 7) * 8;
            size_t go = (size_t)(b * Sn + kt * 64 + r) * Dn + h * DHn + c8;
            uint32_t so = (uint32_t)(r * 72 + c8) * 2;
            *(uint4*)(smem + AT_KH + so) = *(const uint4*)(kh + go);
            *(uint4*)(smem + AT_KL + so) = *(const uint4*)(kl + go);
            *(uint4*)(smem + AT_VH + so) = *(const uint4*)(vh + go);
            *(uint4*)(smem + AT_VL + so) = *(const uint4*)(vl + go);
        }
        if (tid < 64)
            maskb[tid] = (mask[b * Sn + kt * 64 + tid] == 0) ? -1e30f : 0.f;
        __syncthreads();

        // ---- S = Q K^T (3-pass split) ----
        float s[4][4];
#pragma unroll
        for (int nt = 0; nt < 4; nt++)
#pragma unroll
            for (int e = 0; e < 4; e++) s[nt][e] = 0.f;
#pragma unroll
        for (int ks = 0; ks < 4; ks++) {
            uint32_t qhf[4], qlf[4];
            ldsm_x4(qhf[0], qhf[1], qhf[2], qhf[3], sb + AT_QH + aqb + ks * 32);
            ldsm_x4(qlf[0], qlf[1], qlf[2], qlf[3], sb + AT_QL + aqb + ks * 32);
            uint32_t bhf[4][2], blf[4][2];
#pragma unroll
            for (int np = 0; np < 2; np++) {
                uint32_t koff = ((uint32_t)((warp_n * 32 + np * 16 + n_add) * 72
                                            + ks * 16 + k_add)) * 2;
                uint32_t r0, r1, r2, r3;
                ldsm_x4(r0, r1, r2, r3, sb + AT_KH + koff);
                bhf[np * 2][0] = r0; bhf[np * 2][1] = r1;
                bhf[np * 2 + 1][0] = r2; bhf[np * 2 + 1][1] = r3;
                ldsm_x4(r0, r1, r2, r3, sb + AT_KL + koff);
                blf[np * 2][0] = r0; blf[np * 2][1] = r1;
                blf[np * 2 + 1][0] = r2; blf[np * 2 + 1][1] = r3;
            }
#pragma unroll
            for (int nt = 0; nt < 4; nt++) {
                mma16816(s[nt], qhf, bhf[nt]);
                mma16816(s[nt], qhf, blf[nt]);
                mma16816(s[nt], qlf, bhf[nt]);
            }
        }
        // write S tile (scaled to base-2 domain, + mask bias)
#pragma unroll
        for (int nt = 0; nt < 4; nt++) {
            const int col = warp_n * 32 + nt * 8 + tig * 2;
            const float m0 = maskb[col], m1 = maskb[col + 1];
            const int r0 = warp_q * 16 + gid;
            float2 p0; p0.x = s[nt][0] * SC2 + m0; p0.y = s[nt][1] * SC2 + m1;
            float2 p1; p1.x = s[nt][2] * SC2 + m0; p1.y = s[nt][3] * SC2 + m1;
            *(float2*)&Ps[r0 * 68 + col] = p0;
            *(float2*)&Ps[(r0 + 8) * 68 + col] = p1;
        }
        __syncthreads();

        // ---- online softmax (base-2), 4 threads per row; emit P splits ----
        {
            float* prow = Ps + srow * 68 + ssub * 16;
            float mold = mrow[srow];
            float tmax = -1e30f;
#pragma unroll
            for (int j = 0; j < 16; j++) tmax = fmaxf(tmax, prow[j]);
            tmax = fmaxf(tmax, __shfl_xor_sync(0xffffffffu, tmax, 1));
            tmax = fmaxf(tmax, __shfl_xor_sync(0xffffffffu, tmax, 2));
            float mnew = fmaxf(mold, tmax);
            float f = fexp2(mold - mnew);
            float ls = 0.f;
            char* pbh = smem + AT_PBH + (srow * 72 + ssub * 16) * 2;
            char* pbl = smem + AT_PBL + (srow * 72 + ssub * 16) * 2;
#pragma unroll
            for (int j = 0; j < 16; j += 2) {
                float p0 = fexp2(prow[j] - mnew);
                float p1 = fexp2(prow[j + 1] - mnew);
                ls += p0 + p1;
                __nv_bfloat16 h0, l0, h1, l1;
                split_bf16(p0, h0, l0);
                split_bf16(p1, h1, l1);
                *(uint32_t*)(pbh + j * 2) = pack2(h0, h1);
                *(uint32_t*)(pbl + j * 2) = pack2(l0, l1);
            }
            ls += __shfl_xor_sync(0xffffffffu, ls, 1);
            ls += __shfl_xor_sync(0xffffffffu, ls, 2);
            if (ssub == 0) {
                lrow[srow] = lrow[srow] * f + ls;
                mrow[srow] = mnew;
                scl[srow] = f;
            }
        }
        __syncthreads();

        // ---- O = O*f + P V (3-pass split) ----
        {
            const float f0 = scl[warp_q * 16 + gid];
            const float f1 = scl[warp_q * 16 + gid + 8];
#pragma unroll
            for (int nt = 0; nt < 4; nt++) {
                o[nt][0] *= f0; o[nt][1] *= f0;
                o[nt][2] *= f1; o[nt][3] *= f1;
            }
#pragma unroll
            for (int ks = 0; ks < 4; ks++) {
                uint32_t phf[4], plf[4];
                ldsm_x4(phf[0], phf[1], phf[2], phf[3], sb + AT_PBH + aqb + ks * 32);
                ldsm_x4(plf[0], plf[1], plf[2], plf[3], sb + AT_PBL + aqb + ks * 32);
                uint32_t vbh[4][2], vbl[4][2];
#pragma unroll
                for (int np = 0; np < 2; np++) {
                    uint32_t voff = ((uint32_t)((ks * 16 + (lane & 15)) * 72
                                    + warp_n * 32 + np * 16 + ((lane >> 4) & 1) * 8)) * 2;
                    uint32_t r0, r1, r2, r3;
                    ldsm_x4t(r0, r1, r2, r3, sb + AT_VH + voff);
                    vbh[np * 2][0] = r0; vbh[np * 2][1] = r1;
                    vbh[np * 2 + 1][0] = r2; vbh[np * 2 + 1][1] = r3;
                    ldsm_x4t(r0, r1, r2, r3, sb + AT_VL + voff);
                    vbl[np * 2][0] = r0; vbl[np * 2][1] = r1;
                    vbl[np * 2 + 1][0] = r2; vbl[np * 2 + 1][1] = r3;
                }
#pragma unroll
                for (int nt = 0; nt < 4; nt++) {
                    mma16816(o[nt], phf, vbh[nt]);
                    mma16816(o[nt], phf, vbl[nt]);
                    mma16816(o[nt], plf, vbh[nt]);
                }
            }
        }
    }

    // ---- final: normalize and write ctx splits ----
    {
        const int r0 = warp_q * 16 + gid;
        const float inv0 = 1.0f / lrow[r0];
        const float inv1 = 1.0f / lrow[r0 + 8];
#pragma unroll
        for (int nt = 0; nt < 4; nt++) {
            const int col = h * DHn + warp_n * 32 + nt * 8 + tig * 2;
            float e0 = o[nt][0] * inv0, e1 = o[nt][1] * inv0;
            float e2 = o[nt][2] * inv1, e3 = o[nt][3] * inv1;
            __nv_bfloat16 h0, l0, h1, l1, h2, l2, h3, l3;
            split_bf16(e0, h0, l0); split_bf16(e1, h1, l1);
            split_bf16(e2, h2, l2); split_bf16(e3, h3, l3);
            size_t off0 = (rowbase + r0) * Dn + col;
            size_t off1 = (rowbase + r0 + 8) * Dn + col;
            *(uint32_t*)((char*)ctxh + off0 * 2) = pack2(h0, h1);
            *(uint32_t*)((char*)ctxl + off0 * 2) = pack2(l0, l1);
            *(uint32_t*)((char*)ctxh + off1 * 2) = pack2(h2, h3);
            *(uint32_t*)((char*)ctxl + off1 * 2) = pack2(l2, l3);
        }
    }
}

// ---------------- host orchestration ----------------
extern "C" void kernel_launch(void* const* d_in, const int* in_sizes, int n_in,
                              void* d_out, int out_size)
{
    const float* video    = (const float*)d_in[0];
    const float* question = (const float*)d_in[1];
    const int*   mask     = (const int*)  d_in[2];
    const float* pos_emb  = (const float*)d_in[3];
    const float* mod_emb  = (const float*)d_in[4];
    const float* Wv       = (const float*)d_in[5];
    const float* bv       = (const float*)d_in[6];
    const float* nv_g     = (const float*)d_in[7];
    const float* nv_b     = (const float*)d_in[8];
    const float* emb_g    = (const float*)d_in[9];
    const float* emb_b    = (const float*)d_in[10];
    const float* Wq       = (const float*)d_in[11];
    const float* bq       = (const float*)d_in[12];
    const float* Wk       = (const float*)d_in[13];
    const float* bk       = (const float*)d_in[14];
    const float* Wva      = (const float*)d_in[15];
    const float* bva      = (const float*)d_in[16];
    const float* Wo       = (const float*)d_in[17];
    const float* bo       = (const float*)d_in[18];
    const float* ln1_g    = (const float*)d_in[19];
    const float* ln1_b    = (const float*)d_in[20];
    const float* W1       = (const float*)d_in[21];
    const float* b1       = (const float*)d_in[22];
    const float* W2       = (const float*)d_in[23];
    const float* b2       = (const float*)d_in[24];
    const float* ln2_g    = (const float*)d_in[25];
    const float* ln2_b    = (const float*)d_in[26];

    float *x, *t1;
    __nv_bfloat16 *xh, *xl, *aqh, *aql, *akh, *akl, *avh, *avl;
    __nv_bfloat16 *ch, *cl, *hh, *hl, *vh, *vl, *wh, *wl;
    cudaGetSymbolAddress((void**)&x,   g_x);
    cudaGetSymbolAddress((void**)&t1,  g_t1);
    cudaGetSymbolAddress((void**)&xh,  g_xh);  cudaGetSymbolAddress((void**)&xl,  g_xl);
    cudaGetSymbolAddress((void**)&aqh, g_aqh); cudaGetSymbolAddress((void**)&aql, g_aql);
    cudaGetSymbolAddress((void**)&akh, g_akh); cudaGetSymbolAddress((void**)&akl, g_akl);
    cudaGetSymbolAddress((void**)&avh, g_avh); cudaGetSymbolAddress((void**)&avl, g_avl);
    cudaGetSymbolAddress((void**)&ch,  g_ch);  cudaGetSymbolAddress((void**)&cl,  g_cl);
    cudaGetSymbolAddress((void**)&hh,  g_hh);  cudaGetSymbolAddress((void**)&hl,  g_hl);
    cudaGetSymbolAddress((void**)&vh,  g_vh);  cudaGetSymbolAddress((void**)&vl,  g_vl);
    cudaGetSymbolAddress((void**)&wh,  g_wh);  cudaGetSymbolAddress((void**)&wl,  g_wl);

    static bool attr_set = false;
    if (!attr_set) {
        cudaFuncSetAttribute(attn_kernel, cudaFuncAttributeMaxDynamicSharedMemorySize, AT_TOTAL);
        cudaFuncSetAttribute(gemm_bf<0,1>, cudaFuncAttributeMaxDynamicSharedMemorySize, SM_TOTAL);
        cudaFuncSetAttribute(gemm_bf<0,2>, cudaFuncAttributeMaxDynamicSharedMemorySize, SM_TOTAL);
        cudaFuncSetAttribute(gemm_bf<1,2>, cudaFuncAttributeMaxDynamicSharedMemorySize, SM_TOTAL);
        cudaFuncSetAttribute(gemm_bf<2,1>, cudaFuncAttributeMaxDynamicSharedMemorySize, SM_TOTAL);
        attr_set = true;
    }

    // one-shot input splits: video + Wv
    split_kernel<<<(BTr * FDn) / 1024, 256>>>(video, vh, vl);
    split_kernel<<<(FDn * Dn) / 1024, 256>>>(Wv, wh, wl);
    gemm_bf<0,1><<<dim3(Dn / 128, BTr / 128), 256, SM_TOTAL>>>(
        vh, vl, wh, wl, bv, nullptr, t1, nullptr, nullptr, BTr, Dn, FDn);
    ln_kernel<<<BTr, 128>>>(t1, nv_g, nv_b, x, xh, xl, 1);
    embed_ln_kernel<<<BSr, 128>>>(question, pos_emb, mod_emb, emb_g, emb_b, x, xh, xl);

    for (int i = 0; i < NLn; i++) {
        const size_t wD = (size_t)i * Dn * Dn;
        split_kernel<<<(Dn * Dn) / 1024, 256>>>(Wq + wD, wh, wl);
        gemm_bf<0,2><<<dim3(Dn / 128, BSr / 128), 256, SM_TOTAL>>>(
            xh, xl, wh, wl, bq + i * Dn, nullptr, nullptr, aqh, aql, BSr, Dn, Dn);
        split_kernel<<<(Dn * Dn) / 1024, 256>>>(Wk + wD, wh, wl);
        gemm_bf<0,2><<<dim3(Dn / 128, BSr / 128), 256, SM_TOTAL>>>(
            xh, xl, wh, wl, bk + i * Dn, nullptr, nullptr, akh, akl, BSr, Dn, Dn);
        split_kernel<<<(Dn * Dn) / 1024, 256>>>(Wva + wD, wh, wl);
        gemm_bf<0,2><<<dim3(Dn / 128, BSr / 128), 256, SM_TOTAL>>>(
            xh, xl, wh, wl, bva + i * Dn, nullptr, nullptr, avh, avl, BSr, Dn, Dn);

        attn_kernel<<<dim3(Sn / 64, Bn * Hn), 256, AT_TOTAL>>>(
            aqh, aql, akh, akl, avh, avl, mask, ch, cl);

        split_kernel<<<(Dn * Dn) / 1024, 256>>>(Wo + wD, wh, wl);
        gemm_bf<2,1><<<dim3(Dn / 128, BSr / 128), 256, SM_TOTAL>>>(
            ch, cl, wh, wl, bo + i * Dn, x, t1, nullptr, nullptr, BSr, Dn, Dn);
        ln_kernel<<<BSr, 128>>>(t1, ln1_g + i * Dn, ln1_b + i * Dn, x, xh, xl, 0);

        split_kernel<<<(Dn * FFn) / 1024, 256>>>(W1 + (size_t)i * Dn * FFn, wh, wl);
        gemm_bf<1,2><<<dim3(FFn / 128, BSr / 128), 256, SM_TOTAL>>>(
            xh, xl, wh, wl, b1 + i * FFn, nullptr, nullptr, hh, hl, BSr, FFn, Dn);
        split_kernel<<<(FFn * Dn) / 1024, 256>>>(W2 + (size_t)i * FFn * Dn, wh, wl);
        gemm_bf<2,1><<<dim3(Dn / 128, BSr / 128), 256, SM_TOTAL>>>(
            hh, hl, wh, wl, b2 + i * Dn, x, t1, nullptr, nullptr, BSr, Dn, FFn);
        ln_kernel<<<BSr, 128>>>(t1, ln2_g + i * Dn, ln2_b + i * Dn, x, xh, xl, 0);
    }

    cudaMemcpyAsync(d_out, x, (size_t)BSr * Dn * sizeof(float),
                    cudaMemcpyDeviceToDevice, 0);
}